// round 13
// baseline (speedup 1.0000x reference)
#include <cuda_runtime.h>
#include <cuda_fp16.h>
#include <cstdint>
#include <math.h>

// ===========================================================================
// S2Attention on GB300 (sm_103 portable mma.sync path, fp16 numerics)
//   - merged prologue (prep_w + transpose + dw) in one launch
//   - q/out convs: gemm_mma<1>, 2-stage pipeline, 2 blocks/SM
//   - k/v convs: gemm_mma<2> (W hi/lo), 3-stage
//   - attention: single-pass fp16 HMMA, P packed in-loop
// ===========================================================================

#define HWQ  4096
#define NKV  289

// ---------------- device scratch ----------------
__device__ __align__(256) __half g_semT [8L * 4096 * 512];  // [b][tok][512]
__device__ __align__(256) __half g_kpreT[8L * 289 * 512];
__device__ __align__(256) __half g_vpreT[8L * 289 * 512];
__device__ __align__(256) __half g_aoT  [8L * 4096 * 512];
__device__ __align__(256) __half g_qT   [8L * 4096 * 512];  // q*0.125
__device__ __align__(256) __half g_kT   [8L * 289 * 512];
__device__ __align__(256) __half g_vC   [8L * 512 * 296];   // [b][c][296] pad0
__device__ __align__(256) float  g_preK [8L * 289 * 512];   // [b][pos][c]
__device__ __align__(256) float  g_preV [8L * 289 * 512];
__device__ __align__(256) __half g_whi  [3L * 512 * 512];   // 0=wq*0.125,1=wpw,2=wout
__device__ __align__(256) __half g_wlo  [3L * 512 * 512];

// ---------------- helpers ----------------
__device__ __forceinline__ uint32_t smem_u32(const void* p) {
    uint32_t a;
    asm("{ .reg .u64 t; cvta.to.shared.u64 t, %1; cvt.u32.u64 %0, t; }"
        : "=r"(a) : "l"(p));
    return a;
}
__device__ __forceinline__ void mma_f16(float* d, const uint32_t* a, const uint32_t* b) {
    asm volatile(
        "mma.sync.aligned.m16n8k16.row.col.f32.f16.f16.f32 "
        "{%0,%1,%2,%3}, {%4,%5,%6,%7}, {%8,%9}, {%0,%1,%2,%3};"
        : "+f"(d[0]), "+f"(d[1]), "+f"(d[2]), "+f"(d[3])
        : "r"(a[0]), "r"(a[1]), "r"(a[2]), "r"(a[3]), "r"(b[0]), "r"(b[1]));
}
__device__ __forceinline__ void cpa16(uint32_t dst, const void* src, uint32_t nbytes) {
    asm volatile("cp.async.cg.shared.global [%0], [%1], 16, %2;"
                 :: "r"(dst), "l"(src), "r"(nbytes) : "memory");
}
#define CPA_COMMIT() asm volatile("cp.async.commit_group;" ::: "memory")
#define CPA_WAIT0()  asm volatile("cp.async.wait_group 0;" ::: "memory")
#define CPA_WAIT1()  asm volatile("cp.async.wait_group 1;" ::: "memory")

__device__ __forceinline__ uint32_t packh(float hi, float lo) {
    uint32_t r;
    asm("cvt.rn.f16x2.f32 %0, %1, %2;" : "=r"(r) : "f"(hi), "f"(lo));
    return r;
}

// ---------------------------------------------------------------------------
// merged prologue: [0,3072) prep_w | [3072,19456) transpose | [19456,23552) dw
// 256 threads everywhere.
// ---------------------------------------------------------------------------
#define NB_PREP 3072
#define NB_TR   16384
#define NB_DW   4096
#define NB_PRO  (NB_PREP + NB_TR + NB_DW)

__global__ __launch_bounds__(256)
void prologue(const float* __restrict__ sem, const float* __restrict__ spa,
              const float* __restrict__ x,   const float* __restrict__ wq,
              const float* __restrict__ wdw, const float* __restrict__ wpw,
              const float* __restrict__ wout)
{
    __shared__ __align__(16) char pbuf[32768];
    const int bx = blockIdx.x, t = threadIdx.x;

    if (bx < NB_PREP) {
        // ---- weights -> fp16 hi/lo ----
        int i = bx * 256 + t;
        int widx = i >> 18, j = i & 262143;
        float v = (widx == 0) ? wq[j] * 0.125f : (widx == 1) ? wpw[j] : wout[j];
        __half h = __float2half_rn(v);
        g_whi[i] = h;
        g_wlo[i] = __float2half_rn(v - __half2float(h));
        return;
    }
    if (bx < NB_PREP + NB_TR) {
        // ---- transpose sem [b][c][4096] -> g_semT fp16 [b][tok][512] ----
        float (*tile)[33] = (float(*)[33])pbuf;
        int bx2 = bx - NB_PREP;
        int b = bx2 >> 11, rem = bx2 & 2047;
        int n0 = (rem & 127) * 32, c0 = (rem >> 7) * 32;
        int tx = t & 31, ty = t >> 5;
#pragma unroll
        for (int k = 0; k < 4; k++) {
            int c = c0 + ty + 8 * k;
            tile[ty + 8 * k][tx] = sem[((long)b * 512 + c) * 4096 + n0 + tx];
        }
        __syncthreads();
#pragma unroll
        for (int k = 0; k < 4; k++) {
            int n = n0 + ty + 8 * k;
            g_semT[((long)b * 4096 + n) * 512 + c0 + tx] =
                __float2half_rn(tile[tx][ty + 8 * k]);
        }
        return;
    }
    // ---- depthwise conv: 2 channels per block (halves of 128 threads) ----
    {
        int bx3 = bx - NB_PREP - NB_TR;
        int z = bx3 >> 11, rem = bx3 & 2047;
        int b = rem >> 8, cpair = rem & 255;
        const int half = t >> 7, tl = t & 127;
        const int c = cpair * 2 + half;
        const float* in = z ? x : spa;
        float* outp = z ? g_preV : g_preK;
        float* plane = (float*)pbuf + half * 4096;
        const float4* ip = (const float4*)(in + ((long)b * 512 + c) * 4096);
#pragma unroll
        for (int i = tl; i < 1024; i += 128) ((float4*)plane)[i] = ip[i];
        float wr[16];
#pragma unroll
        for (int i = 0; i < 16; i++) wr[i] = wdw[c * 16 + i];
        __syncthreads();

        for (int pos = tl; pos < 289; pos += 128) {
            int oy = pos / 17, ox = pos - oy * 17;
            float acc = 0.f;
#pragma unroll
            for (int ky = 0; ky < 4; ky++) {
                int y = oy * 4 - 2 + ky;
                if ((unsigned)y < 64u) {
#pragma unroll
                    for (int kx = 0; kx < 4; kx++) {
                        int xx = ox * 4 - 2 + kx;
                        if ((unsigned)xx < 64u)
                            acc = fmaf(wr[ky * 4 + kx], plane[y * 64 + xx], acc);
                    }
                }
            }
            outp[((long)b * 289 + pos) * 512 + c] = acc;
        }
    }
}

// ---------------------------------------------------------------------------
// channel LayerNorm per token -> token-major fp16. grid (289,8,2), block 512
// ---------------------------------------------------------------------------
__global__ __launch_bounds__(512)
void ln_kernel(const float* __restrict__ lng, const float* __restrict__ lnb)
{
    const float* inp = blockIdx.z ? g_preV : g_preK;
    __half* oh = blockIdx.z ? g_vpreT : g_kpreT;
    const int pos = blockIdx.x, b = blockIdx.y, c = threadIdx.x;
    float acc = inp[((long)b * 289 + pos) * 512 + c];

    __shared__ float s1[16], s2[16];
    float v1 = acc, v2 = acc * acc;
#pragma unroll
    for (int o = 16; o > 0; o >>= 1) {
        v1 += __shfl_xor_sync(0xffffffffu, v1, o);
        v2 += __shfl_xor_sync(0xffffffffu, v2, o);
    }
    int w = threadIdx.x >> 5, lane = threadIdx.x & 31;
    if (lane == 0) { s1[w] = v1; s2[w] = v2; }
    __syncthreads();
    if (w == 0) {
        v1 = (lane < 16) ? s1[lane] : 0.f;
        v2 = (lane < 16) ? s2[lane] : 0.f;
#pragma unroll
        for (int o = 8; o > 0; o >>= 1) {
            v1 += __shfl_xor_sync(0xffffffffu, v1, o);
            v2 += __shfl_xor_sync(0xffffffffu, v2, o);
        }
        if (lane == 0) { s1[0] = v1; s2[0] = v2; }
    }
    __syncthreads();
    float mean = s1[0] * (1.f / 512.f);
    float var  = s2[0] * (1.f / 512.f) - mean * mean;
    float val  = (acc - mean) * rsqrtf(var + 1e-5f) * lng[c] + lnb[c];
    oh[((long)b * 289 + pos) * 512 + c] = __float2half_rn(val);
}

// ---------------------------------------------------------------------------
// HMMA GEMM: Out[b][tok][co] = sum_ci W[co][ci] * A[b][tok][ci]
// K-chunk 64 = 2x 32-k subtiles. PASSES==1: 2 stages (2 blocks/SM);
// PASSES==2: 3 stages. Subtile: [Whi 10240][(Wlo 10240)?][A 10240]
// ---------------------------------------------------------------------------
template<int PASSES>
__global__ __launch_bounds__(256, 1)
void gemm_mma(int asel, int widx, int osel, float* __restrict__ extOut, int Ntok)
{
    constexpr int SUB    = (PASSES + 1) * 10240;
    constexpr int GSTP   = 2 * SUB;
    constexpr int STAGES = (PASSES == 1) ? 2 : 3;
    extern __shared__ char sm[];
    const uint32_t smb = smem_u32(sm);
    const int t = threadIdx.x, wid = t >> 5, lane = t & 31;
    const int qr = lane >> 2, qc = lane & 3;
    const int b = blockIdx.z & 7, zsel = blockIdx.z >> 3;
    const int m0 = blockIdx.y * 128, n0 = blockIdx.x * 128;
    const int wm = wid >> 2, wn = wid & 3;
    const int aselE = asel + zsel, oselE = osel + zsel;

    const __half* A = (aselE == 0) ? g_semT : (aselE == 1) ? g_kpreT
                    : (aselE == 2) ? g_vpreT : g_aoT;
    A += (long)b * Ntok * 512;
    const __half* Whi = g_whi + (long)widx * 262144;
    const __half* Wlo = g_wlo + (long)widx * 262144;

    float acc[4][4][4];
#pragma unroll
    for (int i = 0; i < 4; i++)
#pragma unroll
        for (int j = 0; j < 4; j++)
#pragma unroll
            for (int k = 0; k < 4; k++) acc[i][j][k] = 0.f;

    auto load_sub = [&](int k0s, uint32_t sb) {
#pragma unroll
        for (int u = 0; u < 2; u++) {
            int q = t + 256 * u;
            int row = q >> 2, cq = q & 3;
            uint32_t soff = (uint32_t)(row * 80 + cq * 16);
            long wof = ((long)(m0 + row) << 9) + k0s + cq * 8;
            cpa16(sb + soff, Whi + wof, 16u);
            if (PASSES == 2) cpa16(sb + 10240 + soff, Wlo + wof, 16u);
            int tok = n0 + row;
            uint32_t asz = (tok < Ntok) ? 16u : 0u;
            long aof = ((long)(asz ? tok : 0) << 9) + k0s + cq * 8;
            cpa16(sb + (PASSES == 2 ? 20480 : 10240) + soff, A + aof, asz);
        }
    };
    auto load_chunk = [&](int c, int stage) {
        uint32_t sb = smb + stage * GSTP;
        load_sub(c * 64, sb);
        load_sub(c * 64 + 32, sb + SUB);
        CPA_COMMIT();
    };

    load_chunk(0, 0);
    load_chunk(1, 1);

    int stage = 0;
    for (int c = 0; c < 8; c++) {
        if (c < 7) { CPA_WAIT1(); } else { CPA_WAIT0(); }
        __syncthreads();

        if (STAGES == 3 && c + 2 < 8) {
            int ns = stage + 2; if (ns >= 3) ns -= 3;
            load_chunk(c + 2, ns);
        }

        const char* stb = sm + stage * GSTP;
#pragma unroll
        for (int sub = 0; sub < 2; sub++) {
            const uint32_t* SW0 = (const uint32_t*)(stb + sub * SUB);
            const uint32_t* SW1 = SW0 + 2560;
            const uint32_t* SA  = SW0 + (PASSES == 2 ? 5120 : 2560);
#pragma unroll
            for (int ks = 0; ks < 2; ks++) {
                uint32_t awh[4][4], bb[4][2];
#pragma unroll
                for (int mt = 0; mt < 4; mt++) {
                    int base = (wm * 64 + mt * 16 + qr) * 20 + qc + ks * 8;
                    awh[mt][0] = SW0[base];       awh[mt][1] = SW0[base + 160];
                    awh[mt][2] = SW0[base + 4];   awh[mt][3] = SW0[base + 164];
                }
#pragma unroll
                for (int nt = 0; nt < 4; nt++) {
                    int bo = (wn * 32 + nt * 8 + qr) * 20 + qc + ks * 8;
                    bb[nt][0] = SA[bo]; bb[nt][1] = SA[bo + 4];
                }
#pragma unroll
                for (int mt = 0; mt < 4; mt++)
#pragma unroll
                    for (int nt = 0; nt < 4; nt++)
                        mma_f16(acc[mt][nt], awh[mt], bb[nt]);
                if (PASSES == 2) {
                    uint32_t awl[4][4];
#pragma unroll
                    for (int mt = 0; mt < 4; mt++) {
                        int base = (wm * 64 + mt * 16 + qr) * 20 + qc + ks * 8;
                        awl[mt][0] = SW1[base];       awl[mt][1] = SW1[base + 160];
                        awl[mt][2] = SW1[base + 4];   awl[mt][3] = SW1[base + 164];
                    }
#pragma unroll
                    for (int mt = 0; mt < 4; mt++)
#pragma unroll
                        for (int nt = 0; nt < 4; nt++)
                            mma_f16(acc[mt][nt], awl[mt], bb[nt]);
                }
            }
        }

        if (STAGES == 2 && c + 2 < 8) {
            __syncthreads();              // all warps done reading this stage
            load_chunk(c + 2, stage);     // reuse the stage just consumed
        }
        stage = (stage + 1 == STAGES) ? 0 : stage + 1;
    }

    // ---- epilogue ----
    __syncthreads();
    float* Osm = (float*)sm;   // [128][132] = 67584 B (fits both GSM variants)
    const bool tokmajor = (oselE < 2);
#pragma unroll
    for (int mt = 0; mt < 4; mt++) {
        int ml = wm * 64 + mt * 16 + qr;
#pragma unroll
        for (int nt = 0; nt < 4; nt++) {
            int nl = wn * 32 + nt * 8 + qc * 2;
            if (tokmajor) {
                Osm[nl * 132 + ml]           = acc[mt][nt][0];
                Osm[(nl + 1) * 132 + ml]     = acc[mt][nt][1];
                Osm[nl * 132 + ml + 8]       = acc[mt][nt][2];
                Osm[(nl + 1) * 132 + ml + 8] = acc[mt][nt][3];
            } else {
                Osm[ml * 132 + nl]           = acc[mt][nt][0];
                Osm[ml * 132 + nl + 1]       = acc[mt][nt][1];
                Osm[(ml + 8) * 132 + nl]     = acc[mt][nt][2];
                Osm[(ml + 8) * 132 + nl + 1] = acc[mt][nt][3];
            }
        }
    }
    __syncthreads();

    if (oselE <= 1) {
        __half* Oh = (oselE == 0) ? g_qT : g_kT;
#pragma unroll 4
        for (int u = 0; u < 64; u++) {
            int idx = t + 256 * u;
            int tl = idx >> 7, co = idx & 127;
            int tok = n0 + tl;
            if (tok < Ntok)
                Oh[((long)b * Ntok + tok) * 512 + m0 + co] =
                    __float2half_rn(Osm[tl * 132 + co]);
        }
    } else if (oselE == 2) {
#pragma unroll 4
        for (int u = 0; u < 64; u++) {
            int idx = t + 256 * u;
            int cl = idx >> 7, tl = idx & 127;
            int tok = n0 + tl;
            if (tok < Ntok)
                g_vC[((long)b * 512 + m0 + cl) * 296 + tok] =
                    __float2half_rn(Osm[cl * 132 + tl]);
        }
    } else {
#pragma unroll 4
        for (int u = 0; u < 64; u++) {
            int idx = t + 256 * u;
            int cl = idx >> 7, tl = idx & 127;
            extOut[((long)b * 512 + m0 + cl) * 4096 + n0 + tl] = Osm[cl * 132 + tl];
        }
    }
}

// ---------------------------------------------------------------------------
// Tensorized attention, single-pass fp16. Block = (bh, 128-token q-tile).
// SQ [0] 128x36w; SK [4608] 296x36w; SV [15264] 64x156w. 25248 w = 100992 B.
// ---------------------------------------------------------------------------
#define SK_  4608
#define SV_  15264
#define ATTN_SMEM (25248 * 4)

__global__ __launch_bounds__(256, 1)
void attn_kernel()
{
    extern __shared__ uint32_t smw[];
    uint4* s4 = (uint4*)smw;
    const int bh = blockIdx.y, b = bh >> 3, hh = bh & 7;
    const int n0 = blockIdx.x * 128;
    const int t = threadIdx.x, w = t >> 5, lane = t & 31;
    const int qr = lane >> 2, qc = lane & 3;

    {
        const uint4* q4 = (const uint4*)(g_qT + ((long)(b * 4096 + n0)) * 512 + hh * 64);
        for (int idx = t; idx < 1024; idx += 256) {
            int row = idx >> 3, j = idx & 7;
            s4[row * 9 + j] = q4[row * 64 + j];
        }
        const uint4* k4 = (const uint4*)(g_kT + ((long)b * 289) * 512 + hh * 64);
        for (int idx = t; idx < 2312; idx += 256) {
            int row = idx >> 3, j = idx & 7;
            s4[SK_ / 4 + row * 9 + j] = k4[row * 64 + j];
        }
        for (int idx = t; idx < 252; idx += 256)
            smw[SK_ + 10404 + idx] = 0;
        const uint4* v4 = (const uint4*)(g_vC + ((long)(b * 512 + hh * 64)) * 296);
        for (int idx = t; idx < 2368; idx += 256) {
            int row = idx / 37, j = idx - row * 37;
            s4[SV_ / 4 + row * 39 + j] = v4[row * 37 + j];
        }
        for (int idx = t; idx < 512; idx += 256) {
            int row = idx >> 3, ww = idx & 7;
            smw[SV_ + row * 156 + 148 + ww] = 0;
        }
    }
    __syncthreads();

    float s[37][4];
#pragma unroll
    for (int nt = 0; nt < 37; nt++)
#pragma unroll
        for (int r = 0; r < 4; r++) s[nt][r] = 0.f;

    const int qrowbase = (w * 16 + qr) * 36 + qc;
#pragma unroll
    for (int kk = 0; kk < 4; kk++) {
        int qb = qrowbase + kk * 8;
        uint32_t a[4] = { smw[qb], smw[qb + 288], smw[qb + 4], smw[qb + 292] };
        int kbase = SK_ + qr * 36 + kk * 8 + qc;
#pragma unroll
        for (int nt = 0; nt < 37; nt++) {
            int kb = kbase + nt * 288;
            uint32_t bb[2] = { smw[kb], smw[kb + 4] };
            mma_f16(s[nt], a, bb);
        }
    }

    float mx0 = -1e30f, mx1 = -1e30f;
#pragma unroll
    for (int nt = 0; nt < 36; nt++) {
        mx0 = fmaxf(mx0, fmaxf(s[nt][0], s[nt][1]));
        mx1 = fmaxf(mx1, fmaxf(s[nt][2], s[nt][3]));
    }
    if (qc == 0) { mx0 = fmaxf(mx0, s[36][0]); mx1 = fmaxf(mx1, s[36][2]); }
    mx0 = fmaxf(mx0, __shfl_xor_sync(0xffffffffu, mx0, 1));
    mx0 = fmaxf(mx0, __shfl_xor_sync(0xffffffffu, mx0, 2));
    mx1 = fmaxf(mx1, __shfl_xor_sync(0xffffffffu, mx1, 1));
    mx1 = fmaxf(mx1, __shfl_xor_sync(0xffffffffu, mx1, 2));

    float sum0 = 0.f, sum1 = 0.f;
#pragma unroll
    for (int nt = 0; nt < 36; nt++) {
        float e0 = __expf(s[nt][0] - mx0), e1 = __expf(s[nt][1] - mx0);
        float e2 = __expf(s[nt][2] - mx1), e3 = __expf(s[nt][3] - mx1);
        s[nt][0] = e0; s[nt][1] = e1; s[nt][2] = e2; s[nt][3] = e3;
        sum0 += e0 + e1; sum1 += e2 + e3;
    }
    {
        float e0 = (qc == 0) ? __expf(s[36][0] - mx0) : 0.f;
        float e2 = (qc == 0) ? __expf(s[36][2] - mx1) : 0.f;
        s[36][0] = e0; s[36][1] = 0.f; s[36][2] = e2; s[36][3] = 0.f;
        sum0 += e0; sum1 += e2;
    }
    sum0 += __shfl_xor_sync(0xffffffffu, sum0, 1);
    sum0 += __shfl_xor_sync(0xffffffffu, sum0, 2);
    sum1 += __shfl_xor_sync(0xffffffffu, sum1, 1);
    sum1 += __shfl_xor_sync(0xffffffffu, sum1, 2);
    float inv0 = 1.f / sum0, inv1 = 1.f / sum1;

#pragma unroll
    for (int nt = 0; nt < 37; nt++) {
        s[nt][0] *= inv0; s[nt][1] *= inv0;
        s[nt][2] *= inv1; s[nt][3] *= inv1;
    }

    float o[8][4];
#pragma unroll
    for (int nt = 0; nt < 8; nt++)
#pragma unroll
        for (int r = 0; r < 4; r++) o[nt][r] = 0.f;

#pragma unroll
    for (int kc = 0; kc < 19; kc++) {
        const int t0 = 2 * kc, t1 = 2 * kc + 1;
        uint32_t a[4];
        a[0] = packh(s[t0][1], s[t0][0]);
        a[1] = packh(s[t0][3], s[t0][2]);
        if (t1 < 37) {
            a[2] = packh(s[t1][1], s[t1][0]);
            a[3] = packh(s[t1][3], s[t1][2]);
        } else {
            a[2] = 0u; a[3] = 0u;
        }
        int vb0 = SV_ + qr * 156 + kc * 8 + qc;
#pragma unroll
        for (int nt = 0; nt < 8; nt++) {
            int vb = vb0 + nt * 1248;
            uint32_t bb[2] = { smw[vb], smw[vb + 4] };
            mma_f16(o[nt], a, bb);
        }
    }

    __syncthreads();
    float* Osm = (float*)smw;   // [128][68]
#pragma unroll
    for (int nt = 0; nt < 8; nt++) {
        int col = nt * 8 + qc * 2;
        int r0 = (w * 16 + qr) * 68;
        Osm[r0 + col]              = o[nt][0];
        Osm[r0 + col + 1]          = o[nt][1];
        Osm[r0 + 8 * 68 + col]     = o[nt][2];
        Osm[r0 + 8 * 68 + col + 1] = o[nt][3];
    }
    __syncthreads();
    for (int idx = t; idx < 8192; idx += 256) {
        int tok = idx >> 6, dc = idx & 63;
        g_aoT[((long)(b * 4096 + n0 + tok)) * 512 + hh * 64 + dc] =
            __float2half_rn(Osm[tok * 68 + dc]);
    }
}

// ---------------------------------------------------------------------------
// launcher
// ---------------------------------------------------------------------------
extern "C" void kernel_launch(void* const* d_in, const int* in_sizes, int n_in,
                              void* d_out, int out_size)
{
    const float* sem  = (const float*)d_in[0];
    const float* spa  = (const float*)d_in[1];
    const float* x    = (const float*)d_in[2];
    const float* wq   = (const float*)d_in[3];
    const float* wdw  = (const float*)d_in[4];
    const float* lng  = (const float*)d_in[5];
    const float* lnb  = (const float*)d_in[6];
    const float* wpw  = (const float*)d_in[7];
    const float* wout = (const float*)d_in[8];
    float* out = (float*)d_out;

    const int GSM1 = 2 * 2 * 2 * 10240;   // 81920  (passes=1, 2 stages)
    const int GSM2 = 3 * 2 * 3 * 10240;   // 184320 (passes=2, 3 stages)
    cudaFuncSetAttribute(gemm_mma<1>, cudaFuncAttributeMaxDynamicSharedMemorySize, GSM1);
    cudaFuncSetAttribute(gemm_mma<2>, cudaFuncAttributeMaxDynamicSharedMemorySize, GSM2);
    cudaFuncSetAttribute(attn_kernel, cudaFuncAttributeMaxDynamicSharedMemorySize, ATTN_SMEM);

    prologue<<<NB_PRO, 256>>>(sem, spa, x, wq, wdw, wpw, wout);
    ln_kernel<<<dim3(289, 8, 2), 512>>>(lng, lnb);

    // q (1-pass)
    gemm_mma<1><<<dim3(32, 4, 8), 256, GSM1>>>(0, 0, 0, nullptr, HWQ);
    // k + v merged (2-pass): z = b + 8*kv
    gemm_mma<2><<<dim3(3, 4, 16), 256, GSM2>>>(1, 1, 1, nullptr, NKV);
    attn_kernel<<<dim3(32, 64), 256, ATTN_SMEM>>>();
    // out (1-pass)
    gemm_mma<1><<<dim3(32, 4, 8), 256, GSM1>>>(3, 2, 3, out, HWQ);
}

// round 14
// speedup vs baseline: 1.0077x; 1.0077x over previous
#include <cuda_runtime.h>
#include <cuda_fp16.h>
#include <cstdint>
#include <math.h>

// ===========================================================================
// S2Attention on GB300 (sm_103 portable mma.sync path, fp16 numerics)
//   - fragment loads via ldmatrix.x4 (LDS-issue was the bottleneck)
//   - q/out convs: gemm_mma<1>; k/v: gemm_mma<2> (W hi/lo)
//   - attention: single-pass fp16 HMMA, P packed in-loop
// ===========================================================================

#define HWQ  4096
#define NKV  289

// ---------------- device scratch ----------------
__device__ __align__(256) __half g_semT [8L * 4096 * 512];  // [b][tok][512]
__device__ __align__(256) __half g_kpreT[8L * 289 * 512];
__device__ __align__(256) __half g_vpreT[8L * 289 * 512];
__device__ __align__(256) __half g_aoT  [8L * 4096 * 512];
__device__ __align__(256) __half g_qT   [8L * 4096 * 512];  // q*0.125
__device__ __align__(256) __half g_kT   [8L * 289 * 512];
__device__ __align__(256) __half g_vC   [8L * 512 * 296];   // [b][c][296] pad0
__device__ __align__(256) float  g_preK [8L * 289 * 512];   // [b][pos][c]
__device__ __align__(256) float  g_preV [8L * 289 * 512];
__device__ __align__(256) __half g_whi  [3L * 512 * 512];   // 0=wq*0.125,1=wpw,2=wout
__device__ __align__(256) __half g_wlo  [3L * 512 * 512];

// ---------------- helpers ----------------
__device__ __forceinline__ uint32_t smem_u32(const void* p) {
    uint32_t a;
    asm("{ .reg .u64 t; cvta.to.shared.u64 t, %1; cvt.u32.u64 %0, t; }"
        : "=r"(a) : "l"(p));
    return a;
}
__device__ __forceinline__ void mma_f16(float* d, const uint32_t* a, const uint32_t* b) {
    asm volatile(
        "mma.sync.aligned.m16n8k16.row.col.f32.f16.f16.f32 "
        "{%0,%1,%2,%3}, {%4,%5,%6,%7}, {%8,%9}, {%0,%1,%2,%3};"
        : "+f"(d[0]), "+f"(d[1]), "+f"(d[2]), "+f"(d[3])
        : "r"(a[0]), "r"(a[1]), "r"(a[2]), "r"(a[3]), "r"(b[0]), "r"(b[1]));
}
#define LDSM4(r, addr) \
    asm volatile("ldmatrix.sync.aligned.m8n8.x4.shared.b16 {%0,%1,%2,%3}, [%4];" \
        : "=r"((r)[0]), "=r"((r)[1]), "=r"((r)[2]), "=r"((r)[3]) : "r"(addr))
#define LDSM2(r, addr) \
    asm volatile("ldmatrix.sync.aligned.m8n8.x2.shared.b16 {%0,%1}, [%2];" \
        : "=r"((r)[0]), "=r"((r)[1]) : "r"(addr))

__device__ __forceinline__ void cpa16(uint32_t dst, const void* src, uint32_t nbytes) {
    asm volatile("cp.async.cg.shared.global [%0], [%1], 16, %2;"
                 :: "r"(dst), "l"(src), "r"(nbytes) : "memory");
}
#define CPA_COMMIT() asm volatile("cp.async.commit_group;" ::: "memory")
#define CPA_WAIT0()  asm volatile("cp.async.wait_group 0;" ::: "memory")
#define CPA_WAIT1()  asm volatile("cp.async.wait_group 1;" ::: "memory")

__device__ __forceinline__ uint32_t packh(float hi, float lo) {
    uint32_t r;
    asm("cvt.rn.f16x2.f32 %0, %1, %2;" : "=r"(r) : "f"(hi), "f"(lo));
    return r;
}

// ---------------------------------------------------------------------------
// merged prologue: [0,3072) prep_w | [3072,19456) transpose | [19456,23552) dw
// ---------------------------------------------------------------------------
#define NB_PREP 3072
#define NB_TR   16384
#define NB_DW   4096
#define NB_PRO  (NB_PREP + NB_TR + NB_DW)

__global__ __launch_bounds__(256)
void prologue(const float* __restrict__ sem, const float* __restrict__ spa,
              const float* __restrict__ x,   const float* __restrict__ wq,
              const float* __restrict__ wdw, const float* __restrict__ wpw,
              const float* __restrict__ wout)
{
    __shared__ __align__(16) char pbuf[32768];
    const int bx = blockIdx.x, t = threadIdx.x;

    if (bx < NB_PREP) {
        int i = bx * 256 + t;
        int widx = i >> 18, j = i & 262143;
        float v = (widx == 0) ? wq[j] * 0.125f : (widx == 1) ? wpw[j] : wout[j];
        __half h = __float2half_rn(v);
        g_whi[i] = h;
        g_wlo[i] = __float2half_rn(v - __half2float(h));
        return;
    }
    if (bx < NB_PREP + NB_TR) {
        float (*tile)[33] = (float(*)[33])pbuf;
        int bx2 = bx - NB_PREP;
        int b = bx2 >> 11, rem = bx2 & 2047;
        int n0 = (rem & 127) * 32, c0 = (rem >> 7) * 32;
        int tx = t & 31, ty = t >> 5;
#pragma unroll
        for (int k = 0; k < 4; k++) {
            int c = c0 + ty + 8 * k;
            tile[ty + 8 * k][tx] = sem[((long)b * 512 + c) * 4096 + n0 + tx];
        }
        __syncthreads();
#pragma unroll
        for (int k = 0; k < 4; k++) {
            int n = n0 + ty + 8 * k;
            g_semT[((long)b * 4096 + n) * 512 + c0 + tx] =
                __float2half_rn(tile[tx][ty + 8 * k]);
        }
        return;
    }
    {
        int bx3 = bx - NB_PREP - NB_TR;
        int z = bx3 >> 11, rem = bx3 & 2047;
        int b = rem >> 8, cpair = rem & 255;
        const int half = t >> 7, tl = t & 127;
        const int c = cpair * 2 + half;
        const float* in = z ? x : spa;
        float* outp = z ? g_preV : g_preK;
        float* plane = (float*)pbuf + half * 4096;
        const float4* ip = (const float4*)(in + ((long)b * 512 + c) * 4096);
#pragma unroll
        for (int i = tl; i < 1024; i += 128) ((float4*)plane)[i] = ip[i];
        float wr[16];
#pragma unroll
        for (int i = 0; i < 16; i++) wr[i] = wdw[c * 16 + i];
        __syncthreads();

        for (int pos = tl; pos < 289; pos += 128) {
            int oy = pos / 17, ox = pos - oy * 17;
            float acc = 0.f;
#pragma unroll
            for (int ky = 0; ky < 4; ky++) {
                int y = oy * 4 - 2 + ky;
                if ((unsigned)y < 64u) {
#pragma unroll
                    for (int kx = 0; kx < 4; kx++) {
                        int xx = ox * 4 - 2 + kx;
                        if ((unsigned)xx < 64u)
                            acc = fmaf(wr[ky * 4 + kx], plane[y * 64 + xx], acc);
                    }
                }
            }
            outp[((long)b * 289 + pos) * 512 + c] = acc;
        }
    }
}

// ---------------------------------------------------------------------------
// channel LayerNorm per token -> token-major fp16. grid (289,8,2), block 512
// ---------------------------------------------------------------------------
__global__ __launch_bounds__(512)
void ln_kernel(const float* __restrict__ lng, const float* __restrict__ lnb)
{
    const float* inp = blockIdx.z ? g_preV : g_preK;
    __half* oh = blockIdx.z ? g_vpreT : g_kpreT;
    const int pos = blockIdx.x, b = blockIdx.y, c = threadIdx.x;
    float acc = inp[((long)b * 289 + pos) * 512 + c];

    __shared__ float s1[16], s2[16];
    float v1 = acc, v2 = acc * acc;
#pragma unroll
    for (int o = 16; o > 0; o >>= 1) {
        v1 += __shfl_xor_sync(0xffffffffu, v1, o);
        v2 += __shfl_xor_sync(0xffffffffu, v2, o);
    }
    int w = threadIdx.x >> 5, lane = threadIdx.x & 31;
    if (lane == 0) { s1[w] = v1; s2[w] = v2; }
    __syncthreads();
    if (w == 0) {
        v1 = (lane < 16) ? s1[lane] : 0.f;
        v2 = (lane < 16) ? s2[lane] : 0.f;
#pragma unroll
        for (int o = 8; o > 0; o >>= 1) {
            v1 += __shfl_xor_sync(0xffffffffu, v1, o);
            v2 += __shfl_xor_sync(0xffffffffu, v2, o);
        }
        if (lane == 0) { s1[0] = v1; s2[0] = v2; }
    }
    __syncthreads();
    float mean = s1[0] * (1.f / 512.f);
    float var  = s2[0] * (1.f / 512.f) - mean * mean;
    float val  = (acc - mean) * rsqrtf(var + 1e-5f) * lng[c] + lnb[c];
    oh[((long)b * 289 + pos) * 512 + c] = __float2half_rn(val);
}

// ---------------------------------------------------------------------------
// HMMA GEMM with ldmatrix fragment loads.
// K-chunk 64 = 2x 32-k subtiles. PASSES==1: 2 stages; PASSES==2: 3 stages.
// Subtile: [Whi 10240][(Wlo 10240)?][A 10240], row stride 80 B.
// ---------------------------------------------------------------------------
template<int PASSES>
__global__ __launch_bounds__(256, 1)
void gemm_mma(int asel, int widx, int osel, float* __restrict__ extOut, int Ntok)
{
    constexpr int SUB    = (PASSES + 1) * 10240;
    constexpr int GSTP   = 2 * SUB;
    constexpr int STAGES = (PASSES == 1) ? 2 : 3;
    constexpr uint32_t AOFF = (PASSES == 2) ? 20480u : 10240u;
    extern __shared__ char sm[];
    const uint32_t smb = smem_u32(sm);
    const int t = threadIdx.x, wid = t >> 5, lane = t & 31;
    const int qr = lane >> 2, qc = lane & 3;
    const int r8 = lane & 7, g = lane >> 3, gh = g & 1, gv = g >> 1;
    const int b = blockIdx.z & 7, zsel = blockIdx.z >> 3;
    const int m0 = blockIdx.y * 128, n0 = blockIdx.x * 128;
    const int wm = wid >> 2, wn = wid & 3;
    const int aselE = asel + zsel, oselE = osel + zsel;

    const __half* A = (aselE == 0) ? g_semT : (aselE == 1) ? g_kpreT
                    : (aselE == 2) ? g_vpreT : g_aoT;
    A += (long)b * Ntok * 512;
    const __half* Whi = g_whi + (long)widx * 262144;
    const __half* Wlo = g_wlo + (long)widx * 262144;

    // ldmatrix per-thread row offsets (bytes)
    const uint32_t wRow = (uint32_t)((wm * 64 + gh * 8 + r8) * 80 + gv * 16);
    const uint32_t aRow = (uint32_t)((wn * 32 + gv * 8 + r8) * 80 + gh * 16);

    float acc[4][4][4];
#pragma unroll
    for (int i = 0; i < 4; i++)
#pragma unroll
        for (int j = 0; j < 4; j++)
#pragma unroll
            for (int k = 0; k < 4; k++) acc[i][j][k] = 0.f;

    auto load_sub = [&](int k0s, uint32_t sb) {
#pragma unroll
        for (int u = 0; u < 2; u++) {
            int q = t + 256 * u;
            int row = q >> 2, cq = q & 3;
            uint32_t soff = (uint32_t)(row * 80 + cq * 16);
            long wof = ((long)(m0 + row) << 9) + k0s + cq * 8;
            cpa16(sb + soff, Whi + wof, 16u);
            if (PASSES == 2) cpa16(sb + 10240 + soff, Wlo + wof, 16u);
            int tok = n0 + row;
            uint32_t asz = (tok < Ntok) ? 16u : 0u;
            long aof = ((long)(asz ? tok : 0) << 9) + k0s + cq * 8;
            cpa16(sb + AOFF + soff, A + aof, asz);
        }
    };
    auto load_chunk = [&](int c, int stage) {
        uint32_t sb = smb + stage * GSTP;
        load_sub(c * 64, sb);
        load_sub(c * 64 + 32, sb + SUB);
        CPA_COMMIT();
    };

    load_chunk(0, 0);
    load_chunk(1, 1);

    int stage = 0;
    for (int c = 0; c < 8; c++) {
        if (c < 7) { CPA_WAIT1(); } else { CPA_WAIT0(); }
        __syncthreads();

        if (STAGES == 3 && c + 2 < 8) {
            int ns = stage + 2; if (ns >= 3) ns -= 3;
            load_chunk(c + 2, ns);
        }

        const uint32_t stb = smb + stage * GSTP;
#pragma unroll
        for (int sub = 0; sub < 2; sub++) {
            const uint32_t subB = stb + sub * SUB;
#pragma unroll
            for (int ks = 0; ks < 2; ks++) {
                uint32_t awh[4][4], bb[4][2];
#pragma unroll
                for (int mt = 0; mt < 4; mt++)
                    LDSM4(awh[mt], subB + wRow + mt * 1280 + ks * 32);
#pragma unroll
                for (int ntp = 0; ntp < 2; ntp++) {
                    uint32_t b4[4];
                    LDSM4(b4, subB + AOFF + aRow + ntp * 1280 + ks * 32);
                    bb[2 * ntp][0]     = b4[0]; bb[2 * ntp][1]     = b4[1];
                    bb[2 * ntp + 1][0] = b4[2]; bb[2 * ntp + 1][1] = b4[3];
                }
#pragma unroll
                for (int mt = 0; mt < 4; mt++)
#pragma unroll
                    for (int nt = 0; nt < 4; nt++)
                        mma_f16(acc[mt][nt], awh[mt], bb[nt]);
                if (PASSES == 2) {
                    uint32_t awl[4][4];
#pragma unroll
                    for (int mt = 0; mt < 4; mt++)
                        LDSM4(awl[mt], subB + 10240 + wRow + mt * 1280 + ks * 32);
#pragma unroll
                    for (int mt = 0; mt < 4; mt++)
#pragma unroll
                        for (int nt = 0; nt < 4; nt++)
                            mma_f16(acc[mt][nt], awl[mt], bb[nt]);
                }
            }
        }

        if (STAGES == 2 && c + 2 < 8) {
            __syncthreads();
            load_chunk(c + 2, stage);
        }
        stage = (stage + 1 == STAGES) ? 0 : stage + 1;
    }

    // ---- epilogue ----
    __syncthreads();
    float* Osm = (float*)sm;   // [128][132] = 67584 B
    const bool tokmajor = (oselE < 2);
#pragma unroll
    for (int mt = 0; mt < 4; mt++) {
        int ml = wm * 64 + mt * 16 + qr;
#pragma unroll
        for (int nt = 0; nt < 4; nt++) {
            int nl = wn * 32 + nt * 8 + qc * 2;
            if (tokmajor) {
                Osm[nl * 132 + ml]           = acc[mt][nt][0];
                Osm[(nl + 1) * 132 + ml]     = acc[mt][nt][1];
                Osm[nl * 132 + ml + 8]       = acc[mt][nt][2];
                Osm[(nl + 1) * 132 + ml + 8] = acc[mt][nt][3];
            } else {
                Osm[ml * 132 + nl]           = acc[mt][nt][0];
                Osm[ml * 132 + nl + 1]       = acc[mt][nt][1];
                Osm[(ml + 8) * 132 + nl]     = acc[mt][nt][2];
                Osm[(ml + 8) * 132 + nl + 1] = acc[mt][nt][3];
            }
        }
    }
    __syncthreads();

    if (oselE <= 1) {
        __half* Oh = (oselE == 0) ? g_qT : g_kT;
#pragma unroll 4
        for (int u = 0; u < 64; u++) {
            int idx = t + 256 * u;
            int tl = idx >> 7, co = idx & 127;
            int tok = n0 + tl;
            if (tok < Ntok)
                Oh[((long)b * Ntok + tok) * 512 + m0 + co] =
                    __float2half_rn(Osm[tl * 132 + co]);
        }
    } else if (oselE == 2) {
#pragma unroll 4
        for (int u = 0; u < 64; u++) {
            int idx = t + 256 * u;
            int cl = idx >> 7, tl = idx & 127;
            int tok = n0 + tl;
            if (tok < Ntok)
                g_vC[((long)b * 512 + m0 + cl) * 296 + tok] =
                    __float2half_rn(Osm[cl * 132 + tl]);
        }
    } else {
#pragma unroll 4
        for (int u = 0; u < 64; u++) {
            int idx = t + 256 * u;
            int cl = idx >> 7, tl = idx & 127;
            extOut[((long)b * 512 + m0 + cl) * 4096 + n0 + tl] = Osm[cl * 132 + tl];
        }
    }
}

// ---------------------------------------------------------------------------
// Tensorized attention with ldmatrix. Block = (bh, 128-token q-tile).
// SQ [0] 128x36w (144 B rows); SK [4608] 296x36w; SV [15264] 64x156w (624 B).
// ---------------------------------------------------------------------------
#define SK_  4608
#define SV_  15264
#define ATTN_SMEM (25248 * 4)

__global__ __launch_bounds__(256, 1)
void attn_kernel()
{
    extern __shared__ uint32_t smw[];
    uint4* s4 = (uint4*)smw;
    const int bh = blockIdx.y, b = bh >> 3, hh = bh & 7;
    const int n0 = blockIdx.x * 128;
    const int t = threadIdx.x, w = t >> 5, lane = t & 31;
    const int qc = lane & 3;
    const int r8 = lane & 7, g = lane >> 3, gh = g & 1, gv = g >> 1;
    const int qr = lane >> 2;
    const uint32_t smbase = smem_u32(smw);

    {
        const uint4* q4 = (const uint4*)(g_qT + ((long)(b * 4096 + n0)) * 512 + hh * 64);
        for (int idx = t; idx < 1024; idx += 256) {
            int row = idx >> 3, j = idx & 7;
            s4[row * 9 + j] = q4[row * 64 + j];
        }
        const uint4* k4 = (const uint4*)(g_kT + ((long)b * 289) * 512 + hh * 64);
        for (int idx = t; idx < 2312; idx += 256) {
            int row = idx >> 3, j = idx & 7;
            s4[SK_ / 4 + row * 9 + j] = k4[row * 64 + j];
        }
        for (int idx = t; idx < 252; idx += 256)
            smw[SK_ + 10404 + idx] = 0;
        const uint4* v4 = (const uint4*)(g_vC + ((long)(b * 512 + hh * 64)) * 296);
        for (int idx = t; idx < 2368; idx += 256) {
            int row = idx / 37, j = idx - row * 37;
            s4[SV_ / 4 + row * 39 + j] = v4[row * 37 + j];
        }
        for (int idx = t; idx < 512; idx += 256) {
            int row = idx >> 3, ww = idx & 7;
            smw[SV_ + row * 156 + 148 + ww] = 0;
        }
    }
    __syncthreads();

    // ldmatrix row addresses (bytes)
    const uint32_t qAddr = smbase + (uint32_t)((w * 16 + gh * 8 + r8) * 144 + gv * 16);
    const uint32_t kAddr = smbase + SK_ * 4 + (uint32_t)((gv * 8 + r8) * 144 + gh * 16);
    const uint32_t kTail = smbase + SK_ * 4 + (uint32_t)((288 + r8) * 144 + gh * 16);
    const uint32_t vAddr = smbase + SV_ * 4 + (uint32_t)((gv * 8 + r8) * 624 + gh * 16);

    // ---- QK^T ----
    float s[37][4];
#pragma unroll
    for (int nt = 0; nt < 37; nt++)
#pragma unroll
        for (int r = 0; r < 4; r++) s[nt][r] = 0.f;

#pragma unroll
    for (int kk = 0; kk < 4; kk++) {
        uint32_t a[4];
        LDSM4(a, qAddr + kk * 32);
#pragma unroll
        for (int ntp = 0; ntp < 18; ntp++) {
            uint32_t b4[4];
            LDSM4(b4, kAddr + ntp * 2304 + kk * 32);
            mma_f16(s[2 * ntp],     a, b4);
            mma_f16(s[2 * ntp + 1], a, b4 + 2);
        }
        {   // tile 36 (rows 288..295)
            uint32_t b2[2];
            LDSM2(b2, kTail + kk * 32);
            mma_f16(s[36], a, b2);
        }
    }

    // ---- softmax ----
    float mx0 = -1e30f, mx1 = -1e30f;
#pragma unroll
    for (int nt = 0; nt < 36; nt++) {
        mx0 = fmaxf(mx0, fmaxf(s[nt][0], s[nt][1]));
        mx1 = fmaxf(mx1, fmaxf(s[nt][2], s[nt][3]));
    }
    if (qc == 0) { mx0 = fmaxf(mx0, s[36][0]); mx1 = fmaxf(mx1, s[36][2]); }
    mx0 = fmaxf(mx0, __shfl_xor_sync(0xffffffffu, mx0, 1));
    mx0 = fmaxf(mx0, __shfl_xor_sync(0xffffffffu, mx0, 2));
    mx1 = fmaxf(mx1, __shfl_xor_sync(0xffffffffu, mx1, 1));
    mx1 = fmaxf(mx1, __shfl_xor_sync(0xffffffffu, mx1, 2));

    float sum0 = 0.f, sum1 = 0.f;
#pragma unroll
    for (int nt = 0; nt < 36; nt++) {
        float e0 = __expf(s[nt][0] - mx0), e1 = __expf(s[nt][1] - mx0);
        float e2 = __expf(s[nt][2] - mx1), e3 = __expf(s[nt][3] - mx1);
        s[nt][0] = e0; s[nt][1] = e1; s[nt][2] = e2; s[nt][3] = e3;
        sum0 += e0 + e1; sum1 += e2 + e3;
    }
    {
        float e0 = (qc == 0) ? __expf(s[36][0] - mx0) : 0.f;
        float e2 = (qc == 0) ? __expf(s[36][2] - mx1) : 0.f;
        s[36][0] = e0; s[36][1] = 0.f; s[36][2] = e2; s[36][3] = 0.f;
        sum0 += e0; sum1 += e2;
    }
    sum0 += __shfl_xor_sync(0xffffffffu, sum0, 1);
    sum0 += __shfl_xor_sync(0xffffffffu, sum0, 2);
    sum1 += __shfl_xor_sync(0xffffffffu, sum1, 1);
    sum1 += __shfl_xor_sync(0xffffffffu, sum1, 2);
    float inv0 = 1.f / sum0, inv1 = 1.f / sum1;

#pragma unroll
    for (int nt = 0; nt < 37; nt++) {
        s[nt][0] *= inv0; s[nt][1] *= inv0;
        s[nt][2] *= inv1; s[nt][3] *= inv1;
    }

    // ---- AV: P packed on the fly, V via ldmatrix ----
    float o[8][4];
#pragma unroll
    for (int nt = 0; nt < 8; nt++)
#pragma unroll
        for (int r = 0; r < 4; r++) o[nt][r] = 0.f;

#pragma unroll
    for (int kc = 0; kc < 19; kc++) {
        const int t0 = 2 * kc, t1 = 2 * kc + 1;
        uint32_t a[4];
        a[0] = packh(s[t0][1], s[t0][0]);
        a[1] = packh(s[t0][3], s[t0][2]);
        if (t1 < 37) {
            a[2] = packh(s[t1][1], s[t1][0]);
            a[3] = packh(s[t1][3], s[t1][2]);
        } else {
            a[2] = 0u; a[3] = 0u;
        }
#pragma unroll
        for (int ntp = 0; ntp < 4; ntp++) {
            uint32_t b4[4];
            LDSM4(b4, vAddr + ntp * 9984 + kc * 32);
            mma_f16(o[2 * ntp],     a, b4);
            mma_f16(o[2 * ntp + 1], a, b4 + 2);
        }
    }

    // ---- stage + store (token-major fp16) ----
    __syncthreads();
    float* Osm = (float*)smw;   // [128][68]
#pragma unroll
    for (int nt = 0; nt < 8; nt++) {
        int col = nt * 8 + qc * 2;
        int r0 = (w * 16 + qr) * 68;
        Osm[r0 + col]              = o[nt][0];
        Osm[r0 + col + 1]          = o[nt][1];
        Osm[r0 + 8 * 68 + col]     = o[nt][2];
        Osm[r0 + 8 * 68 + col + 1] = o[nt][3];
    }
    __syncthreads();
    for (int idx = t; idx < 8192; idx += 256) {
        int tok = idx >> 6, dc = idx & 63;
        g_aoT[((long)(b * 4096 + n0 + tok)) * 512 + hh * 64 + dc] =
            __float2half_rn(Osm[tok * 68 + dc]);
    }
}

// ---------------------------------------------------------------------------
// launcher
// ---------------------------------------------------------------------------
extern "C" void kernel_launch(void* const* d_in, const int* in_sizes, int n_in,
                              void* d_out, int out_size)
{
    const float* sem  = (const float*)d_in[0];
    const float* spa  = (const float*)d_in[1];
    const float* x    = (const float*)d_in[2];
    const float* wq   = (const float*)d_in[3];
    const float* wdw  = (const float*)d_in[4];
    const float* lng  = (const float*)d_in[5];
    const float* lnb  = (const float*)d_in[6];
    const float* wpw  = (const float*)d_in[7];
    const float* wout = (const float*)d_in[8];
    float* out = (float*)d_out;

    const int GSM1 = 2 * 2 * 2 * 10240;   // 81920  (passes=1, 2 stages)
    const int GSM2 = 3 * 2 * 3 * 10240;   // 184320 (passes=2, 3 stages)
    cudaFuncSetAttribute(gemm_mma<1>, cudaFuncAttributeMaxDynamicSharedMemorySize, GSM1);
    cudaFuncSetAttribute(gemm_mma<2>, cudaFuncAttributeMaxDynamicSharedMemorySize, GSM2);
    cudaFuncSetAttribute(attn_kernel, cudaFuncAttributeMaxDynamicSharedMemorySize, ATTN_SMEM);

    prologue<<<NB_PRO, 256>>>(sem, spa, x, wq, wdw, wpw, wout);
    ln_kernel<<<dim3(289, 8, 2), 512>>>(lng, lnb);

    // q (1-pass)
    gemm_mma<1><<<dim3(32, 4, 8), 256, GSM1>>>(0, 0, 0, nullptr, HWQ);
    // k + v merged (2-pass): z = b + 8*kv
    gemm_mma<2><<<dim3(3, 4, 16), 256, GSM2>>>(1, 1, 1, nullptr, NKV);
    attn_kernel<<<dim3(32, 64), 256, ATTN_SMEM>>>();
    // out (1-pass)
    gemm_mma<1><<<dim3(32, 4, 8), 256, GSM1>>>(3, 2, 3, out, HWQ);
}

// round 15
// speedup vs baseline: 1.0411x; 1.0331x over previous
#include <cuda_runtime.h>
#include <cuda_fp16.h>
#include <cstdint>
#include <math.h>

// ===========================================================================
// S2Attention on GB300 (sm_103 portable mma.sync path, fp16 numerics)
//   - fused q/k/v GEMM launch (q,k 1-pass; v 2-pass W hi/lo), ldmatrix frags
//   - attention: single-pass fp16 HMMA, P packed in-loop
// ===========================================================================

#define HWQ  4096
#define NKV  289

// ---------------- device scratch ----------------
__device__ __align__(256) __half g_semT [8L * 4096 * 512];  // [b][tok][512]
__device__ __align__(256) __half g_kpreT[8L * 289 * 512];
__device__ __align__(256) __half g_vpreT[8L * 289 * 512];
__device__ __align__(256) __half g_aoT  [8L * 4096 * 512];
__device__ __align__(256) __half g_qT   [8L * 4096 * 512];  // q*0.125
__device__ __align__(256) __half g_kT   [8L * 289 * 512];
__device__ __align__(256) __half g_vC   [8L * 512 * 296];   // [b][c][296] pad0
__device__ __align__(256) float  g_preK [8L * 289 * 512];   // [b][pos][c]
__device__ __align__(256) float  g_preV [8L * 289 * 512];
__device__ __align__(256) __half g_whi  [3L * 512 * 512];   // 0=wq*0.125,1=wpw,2=wout
__device__ __align__(256) __half g_wlo  [3L * 512 * 512];

// ---------------- helpers ----------------
__device__ __forceinline__ uint32_t smem_u32(const void* p) {
    uint32_t a;
    asm("{ .reg .u64 t; cvta.to.shared.u64 t, %1; cvt.u32.u64 %0, t; }"
        : "=r"(a) : "l"(p));
    return a;
}
__device__ __forceinline__ void mma_f16(float* d, const uint32_t* a, const uint32_t* b) {
    asm volatile(
        "mma.sync.aligned.m16n8k16.row.col.f32.f16.f16.f32 "
        "{%0,%1,%2,%3}, {%4,%5,%6,%7}, {%8,%9}, {%0,%1,%2,%3};"
        : "+f"(d[0]), "+f"(d[1]), "+f"(d[2]), "+f"(d[3])
        : "r"(a[0]), "r"(a[1]), "r"(a[2]), "r"(a[3]), "r"(b[0]), "r"(b[1]));
}
#define LDSM4(r, addr) \
    asm volatile("ldmatrix.sync.aligned.m8n8.x4.shared.b16 {%0,%1,%2,%3}, [%4];" \
        : "=r"((r)[0]), "=r"((r)[1]), "=r"((r)[2]), "=r"((r)[3]) : "r"(addr))
#define LDSM2(r, addr) \
    asm volatile("ldmatrix.sync.aligned.m8n8.x2.shared.b16 {%0,%1}, [%2];" \
        : "=r"((r)[0]), "=r"((r)[1]) : "r"(addr))

__device__ __forceinline__ void cpa16(uint32_t dst, const void* src, uint32_t nbytes) {
    asm volatile("cp.async.cg.shared.global [%0], [%1], 16, %2;"
                 :: "r"(dst), "l"(src), "r"(nbytes) : "memory");
}
#define CPA_COMMIT() asm volatile("cp.async.commit_group;" ::: "memory")
#define CPA_WAIT0()  asm volatile("cp.async.wait_group 0;" ::: "memory")
#define CPA_WAIT1()  asm volatile("cp.async.wait_group 1;" ::: "memory")

__device__ __forceinline__ uint32_t packh(float hi, float lo) {
    uint32_t r;
    asm("cvt.rn.f16x2.f32 %0, %1, %2;" : "=r"(r) : "f"(hi), "f"(lo));
    return r;
}

// ---------------------------------------------------------------------------
// merged prologue: [0,3072) prep_w | [3072,19456) transpose | [19456,23552) dw
// ---------------------------------------------------------------------------
#define NB_PREP 3072
#define NB_TR   16384
#define NB_DW   4096
#define NB_PRO  (NB_PREP + NB_TR + NB_DW)

__global__ __launch_bounds__(256)
void prologue(const float* __restrict__ sem, const float* __restrict__ spa,
              const float* __restrict__ x,   const float* __restrict__ wq,
              const float* __restrict__ wdw, const float* __restrict__ wpw,
              const float* __restrict__ wout)
{
    __shared__ __align__(16) char pbuf[32768];
    const int bx = blockIdx.x, t = threadIdx.x;

    if (bx < NB_PREP) {
        int i = bx * 256 + t;
        int widx = i >> 18, j = i & 262143;
        float v = (widx == 0) ? wq[j] * 0.125f : (widx == 1) ? wpw[j] : wout[j];
        __half h = __float2half_rn(v);
        g_whi[i] = h;
        g_wlo[i] = __float2half_rn(v - __half2float(h));
        return;
    }
    if (bx < NB_PREP + NB_TR) {
        float (*tile)[33] = (float(*)[33])pbuf;
        int bx2 = bx - NB_PREP;
        int b = bx2 >> 11, rem = bx2 & 2047;
        int n0 = (rem & 127) * 32, c0 = (rem >> 7) * 32;
        int tx = t & 31, ty = t >> 5;
#pragma unroll
        for (int k = 0; k < 4; k++) {
            int c = c0 + ty + 8 * k;
            tile[ty + 8 * k][tx] = sem[((long)b * 512 + c) * 4096 + n0 + tx];
        }
        __syncthreads();
#pragma unroll
        for (int k = 0; k < 4; k++) {
            int n = n0 + ty + 8 * k;
            g_semT[((long)b * 4096 + n) * 512 + c0 + tx] =
                __float2half_rn(tile[tx][ty + 8 * k]);
        }
        return;
    }
    {
        int bx3 = bx - NB_PREP - NB_TR;
        int z = bx3 >> 11, rem = bx3 & 2047;
        int b = rem >> 8, cpair = rem & 255;
        const int half = t >> 7, tl = t & 127;
        const int c = cpair * 2 + half;
        const float* in = z ? x : spa;
        float* outp = z ? g_preV : g_preK;
        float* plane = (float*)pbuf + half * 4096;
        const float4* ip = (const float4*)(in + ((long)b * 512 + c) * 4096);
#pragma unroll
        for (int i = tl; i < 1024; i += 128) ((float4*)plane)[i] = ip[i];
        float wr[16];
#pragma unroll
        for (int i = 0; i < 16; i++) wr[i] = wdw[c * 16 + i];
        __syncthreads();

        for (int pos = tl; pos < 289; pos += 128) {
            int oy = pos / 17, ox = pos - oy * 17;
            float acc = 0.f;
#pragma unroll
            for (int ky = 0; ky < 4; ky++) {
                int y = oy * 4 - 2 + ky;
                if ((unsigned)y < 64u) {
#pragma unroll
                    for (int kx = 0; kx < 4; kx++) {
                        int xx = ox * 4 - 2 + kx;
                        if ((unsigned)xx < 64u)
                            acc = fmaf(wr[ky * 4 + kx], plane[y * 64 + xx], acc);
                    }
                }
            }
            outp[((long)b * 289 + pos) * 512 + c] = acc;
        }
    }
}

// ---------------------------------------------------------------------------
// channel LayerNorm per token -> token-major fp16. grid (289,8,2), block 512
// ---------------------------------------------------------------------------
__global__ __launch_bounds__(512)
void ln_kernel(const float* __restrict__ lng, const float* __restrict__ lnb)
{
    const float* inp = blockIdx.z ? g_preV : g_preK;
    __half* oh = blockIdx.z ? g_vpreT : g_kpreT;
    const int pos = blockIdx.x, b = blockIdx.y, c = threadIdx.x;
    float acc = inp[((long)b * 289 + pos) * 512 + c];

    __shared__ float s1[16], s2[16];
    float v1 = acc, v2 = acc * acc;
#pragma unroll
    for (int o = 16; o > 0; o >>= 1) {
        v1 += __shfl_xor_sync(0xffffffffu, v1, o);
        v2 += __shfl_xor_sync(0xffffffffu, v2, o);
    }
    int w = threadIdx.x >> 5, lane = threadIdx.x & 31;
    if (lane == 0) { s1[w] = v1; s2[w] = v2; }
    __syncthreads();
    if (w == 0) {
        v1 = (lane < 16) ? s1[lane] : 0.f;
        v2 = (lane < 16) ? s2[lane] : 0.f;
#pragma unroll
        for (int o = 8; o > 0; o >>= 1) {
            v1 += __shfl_xor_sync(0xffffffffu, v1, o);
            v2 += __shfl_xor_sync(0xffffffffu, v2, o);
        }
        if (lane == 0) { s1[0] = v1; s2[0] = v2; }
    }
    __syncthreads();
    float mean = s1[0] * (1.f / 512.f);
    float var  = s2[0] * (1.f / 512.f) - mean * mean;
    float val  = (acc - mean) * rsqrtf(var + 1e-5f) * lng[c] + lnb[c];
    oh[((long)b * 289 + pos) * 512 + c] = __float2half_rn(val);
}

// ---------------------------------------------------------------------------
// GEMM body (device fn): Out[b][tok][co] = sum_ci W[co][ci] * A[b][tok][ci]
// K-chunk 64 = 2x 32-k subtiles, ldmatrix fragments.
// PASSES==1: 2 stages; PASSES==2: 3 stages.
// ---------------------------------------------------------------------------
template<int PASSES>
__device__ __forceinline__
void gemm_body(char* sm, const __half* A /*already + b offset*/,
               const __half* Whi, const __half* Wlo,
               int oselE, int b, int Ntok, float* __restrict__ extOut)
{
    constexpr int SUB    = (PASSES + 1) * 10240;
    constexpr int GSTP   = 2 * SUB;
    constexpr int STAGES = (PASSES == 1) ? 2 : 3;
    constexpr uint32_t AOFF = (PASSES == 2) ? 20480u : 10240u;
    const uint32_t smb = smem_u32(sm);
    const int t = threadIdx.x, wid = t >> 5, lane = t & 31;
    const int qr = lane >> 2, qc = lane & 3;
    const int r8 = lane & 7, g = lane >> 3, gh = g & 1, gv = g >> 1;
    const int m0 = blockIdx.y * 128, n0 = blockIdx.x * 128;
    const int wm = wid >> 2, wn = wid & 3;

    const uint32_t wRow = (uint32_t)((wm * 64 + gh * 8 + r8) * 80 + gv * 16);
    const uint32_t aRow = (uint32_t)((wn * 32 + gv * 8 + r8) * 80 + gh * 16);

    float acc[4][4][4];
#pragma unroll
    for (int i = 0; i < 4; i++)
#pragma unroll
        for (int j = 0; j < 4; j++)
#pragma unroll
            for (int k = 0; k < 4; k++) acc[i][j][k] = 0.f;

    auto load_sub = [&](int k0s, uint32_t sb) {
#pragma unroll
        for (int u = 0; u < 2; u++) {
            int q = t + 256 * u;
            int row = q >> 2, cq = q & 3;
            uint32_t soff = (uint32_t)(row * 80 + cq * 16);
            long wof = ((long)(m0 + row) << 9) + k0s + cq * 8;
            cpa16(sb + soff, Whi + wof, 16u);
            if (PASSES == 2) cpa16(sb + 10240 + soff, Wlo + wof, 16u);
            int tok = n0 + row;
            uint32_t asz = (tok < Ntok) ? 16u : 0u;
            long aof = ((long)(asz ? tok : 0) << 9) + k0s + cq * 8;
            cpa16(sb + AOFF + soff, A + aof, asz);
        }
    };
    auto load_chunk = [&](int c, int stage) {
        uint32_t sb = smb + stage * GSTP;
        load_sub(c * 64, sb);
        load_sub(c * 64 + 32, sb + SUB);
        CPA_COMMIT();
    };

    load_chunk(0, 0);
    load_chunk(1, 1);

    int stage = 0;
    for (int c = 0; c < 8; c++) {
        if (c < 7) { CPA_WAIT1(); } else { CPA_WAIT0(); }
        __syncthreads();

        if (STAGES == 3 && c + 2 < 8) {
            int ns = stage + 2; if (ns >= 3) ns -= 3;
            load_chunk(c + 2, ns);
        }

        const uint32_t stb = smb + stage * GSTP;
#pragma unroll
        for (int sub = 0; sub < 2; sub++) {
            const uint32_t subB = stb + sub * SUB;
#pragma unroll
            for (int ks = 0; ks < 2; ks++) {
                uint32_t awh[4][4], bb[4][2];
#pragma unroll
                for (int mt = 0; mt < 4; mt++)
                    LDSM4(awh[mt], subB + wRow + mt * 1280 + ks * 32);
#pragma unroll
                for (int ntp = 0; ntp < 2; ntp++) {
                    uint32_t b4[4];
                    LDSM4(b4, subB + AOFF + aRow + ntp * 1280 + ks * 32);
                    bb[2 * ntp][0]     = b4[0]; bb[2 * ntp][1]     = b4[1];
                    bb[2 * ntp + 1][0] = b4[2]; bb[2 * ntp + 1][1] = b4[3];
                }
#pragma unroll
                for (int mt = 0; mt < 4; mt++)
#pragma unroll
                    for (int nt = 0; nt < 4; nt++)
                        mma_f16(acc[mt][nt], awh[mt], bb[nt]);
                if (PASSES == 2) {
                    uint32_t awl[4][4];
#pragma unroll
                    for (int mt = 0; mt < 4; mt++)
                        LDSM4(awl[mt], subB + 10240 + wRow + mt * 1280 + ks * 32);
#pragma unroll
                    for (int mt = 0; mt < 4; mt++)
#pragma unroll
                        for (int nt = 0; nt < 4; nt++)
                            mma_f16(acc[mt][nt], awl[mt], bb[nt]);
                }
            }
        }

        if (STAGES == 2 && c + 2 < 8) {
            __syncthreads();
            load_chunk(c + 2, stage);
        }
        stage = (stage + 1 == STAGES) ? 0 : stage + 1;
    }

    // ---- epilogue ----
    __syncthreads();
    float* Osm = (float*)sm;   // [128][132] = 67584 B
    const bool tokmajor = (oselE < 2);
#pragma unroll
    for (int mt = 0; mt < 4; mt++) {
        int ml = wm * 64 + mt * 16 + qr;
#pragma unroll
        for (int nt = 0; nt < 4; nt++) {
            int nl = wn * 32 + nt * 8 + qc * 2;
            if (tokmajor) {
                Osm[nl * 132 + ml]           = acc[mt][nt][0];
                Osm[(nl + 1) * 132 + ml]     = acc[mt][nt][1];
                Osm[nl * 132 + ml + 8]       = acc[mt][nt][2];
                Osm[(nl + 1) * 132 + ml + 8] = acc[mt][nt][3];
            } else {
                Osm[ml * 132 + nl]           = acc[mt][nt][0];
                Osm[ml * 132 + nl + 1]       = acc[mt][nt][1];
                Osm[(ml + 8) * 132 + nl]     = acc[mt][nt][2];
                Osm[(ml + 8) * 132 + nl + 1] = acc[mt][nt][3];
            }
        }
    }
    __syncthreads();

    if (oselE <= 1) {
        __half* Oh = (oselE == 0) ? g_qT : g_kT;
#pragma unroll 4
        for (int u = 0; u < 64; u++) {
            int idx = t + 256 * u;
            int tl = idx >> 7, co = idx & 127;
            int tok = n0 + tl;
            if (tok < Ntok)
                Oh[((long)b * Ntok + tok) * 512 + m0 + co] =
                    __float2half_rn(Osm[tl * 132 + co]);
        }
    } else if (oselE == 2) {
#pragma unroll 4
        for (int u = 0; u < 64; u++) {
            int idx = t + 256 * u;
            int cl = idx >> 7, tl = idx & 127;
            int tok = n0 + tl;
            if (tok < Ntok)
                g_vC[((long)b * 512 + m0 + cl) * 296 + tok] =
                    __float2half_rn(Osm[cl * 132 + tl]);
        }
    } else {
#pragma unroll 4
        for (int u = 0; u < 64; u++) {
            int idx = t + 256 * u;
            int cl = idx >> 7, tl = idx & 127;
            extOut[((long)b * 512 + m0 + cl) * 4096 + n0 + tl] = Osm[cl * 132 + tl];
        }
    }
}

// fused q + k + v GEMM launch. grid (32, 4, 24):
//   z 0..7  : q (1-pass, Ntok=4096)
//   z 8..15 : k (1-pass, Ntok=289, x<3)
//   z 16..23: v (2-pass, Ntok=289, x<3)
__global__ __launch_bounds__(256, 1)
void gemm_qkv()
{
    extern __shared__ char sm[];
    const int z = blockIdx.z;
    if (z < 8) {
        gemm_body<1>(sm, g_semT + (long)z * HWQ * 512, g_whi, g_wlo,
                     0, z, HWQ, nullptr);
    } else if (z < 16) {
        if (blockIdx.x >= 3) return;
        int b = z - 8;
        gemm_body<1>(sm, g_kpreT + (long)b * NKV * 512,
                     g_whi + 262144, g_wlo + 262144, 1, b, NKV, nullptr);
    } else {
        if (blockIdx.x >= 3) return;
        int b = z - 16;
        gemm_body<2>(sm, g_vpreT + (long)b * NKV * 512,
                     g_whi + 262144, g_wlo + 262144, 2, b, NKV, nullptr);
    }
}

// out GEMM launch. grid (32, 4, 8).
__global__ __launch_bounds__(256, 1)
void gemm_out(float* __restrict__ out)
{
    extern __shared__ char sm[];
    const int b = blockIdx.z;
    gemm_body<1>(sm, g_aoT + (long)b * HWQ * 512,
                 g_whi + 2 * 262144, g_wlo + 2 * 262144, 3, b, HWQ, out);
}

// ---------------------------------------------------------------------------
// Tensorized attention with ldmatrix. Block = (bh, 128-token q-tile).
// SQ [0] 128x36w (144 B rows); SK [4608] 296x36w; SV [15264] 64x156w (624 B).
// ---------------------------------------------------------------------------
#define SK_  4608
#define SV_  15264
#define ATTN_SMEM (25248 * 4)

__global__ __launch_bounds__(256, 1)
void attn_kernel()
{
    extern __shared__ uint32_t smw[];
    uint4* s4 = (uint4*)smw;
    const int bh = blockIdx.y, b = bh >> 3, hh = bh & 7;
    const int n0 = blockIdx.x * 128;
    const int t = threadIdx.x, w = t >> 5, lane = t & 31;
    const int qc = lane & 3;
    const int r8 = lane & 7, g = lane >> 3, gh = g & 1, gv = g >> 1;
    const int qr = lane >> 2;
    const uint32_t smbase = smem_u32(smw);

    {
        const uint4* q4 = (const uint4*)(g_qT + ((long)(b * 4096 + n0)) * 512 + hh * 64);
        for (int idx = t; idx < 1024; idx += 256) {
            int row = idx >> 3, j = idx & 7;
            s4[row * 9 + j] = q4[row * 64 + j];
        }
        const uint4* k4 = (const uint4*)(g_kT + ((long)b * 289) * 512 + hh * 64);
        for (int idx = t; idx < 2312; idx += 256) {
            int row = idx >> 3, j = idx & 7;
            s4[SK_ / 4 + row * 9 + j] = k4[row * 64 + j];
        }
        for (int idx = t; idx < 252; idx += 256)
            smw[SK_ + 10404 + idx] = 0;
        const uint4* v4 = (const uint4*)(g_vC + ((long)(b * 512 + hh * 64)) * 296);
        for (int idx = t; idx < 2368; idx += 256) {
            int row = idx / 37, j = idx - row * 37;
            s4[SV_ / 4 + row * 39 + j] = v4[row * 37 + j];
        }
        for (int idx = t; idx < 512; idx += 256) {
            int row = idx >> 3, ww = idx & 7;
            smw[SV_ + row * 156 + 148 + ww] = 0;
        }
    }
    __syncthreads();

    const uint32_t qAddr = smbase + (uint32_t)((w * 16 + gh * 8 + r8) * 144 + gv * 16);
    const uint32_t kAddr = smbase + SK_ * 4 + (uint32_t)((gv * 8 + r8) * 144 + gh * 16);
    const uint32_t kTail = smbase + SK_ * 4 + (uint32_t)((288 + r8) * 144 + gh * 16);
    const uint32_t vAddr = smbase + SV_ * 4 + (uint32_t)((gv * 8 + r8) * 624 + gh * 16);

    float s[37][4];
#pragma unroll
    for (int nt = 0; nt < 37; nt++)
#pragma unroll
        for (int r = 0; r < 4; r++) s[nt][r] = 0.f;

#pragma unroll
    for (int kk = 0; kk < 4; kk++) {
        uint32_t a[4];
        LDSM4(a, qAddr + kk * 32);
#pragma unroll
        for (int ntp = 0; ntp < 18; ntp++) {
            uint32_t b4[4];
            LDSM4(b4, kAddr + ntp * 2304 + kk * 32);
            mma_f16(s[2 * ntp],     a, b4);
            mma_f16(s[2 * ntp + 1], a, b4 + 2);
        }
        {
            uint32_t b2[2];
            LDSM2(b2, kTail + kk * 32);
            mma_f16(s[36], a, b2);
        }
    }

    float mx0 = -1e30f, mx1 = -1e30f;
#pragma unroll
    for (int nt = 0; nt < 36; nt++) {
        mx0 = fmaxf(mx0, fmaxf(s[nt][0], s[nt][1]));
        mx1 = fmaxf(mx1, fmaxf(s[nt][2], s[nt][3]));
    }
    if (qc == 0) { mx0 = fmaxf(mx0, s[36][0]); mx1 = fmaxf(mx1, s[36][2]); }
    mx0 = fmaxf(mx0, __shfl_xor_sync(0xffffffffu, mx0, 1));
    mx0 = fmaxf(mx0, __shfl_xor_sync(0xffffffffu, mx0, 2));
    mx1 = fmaxf(mx1, __shfl_xor_sync(0xffffffffu, mx1, 1));
    mx1 = fmaxf(mx1, __shfl_xor_sync(0xffffffffu, mx1, 2));

    float sum0 = 0.f, sum1 = 0.f;
#pragma unroll
    for (int nt = 0; nt < 36; nt++) {
        float e0 = __expf(s[nt][0] - mx0), e1 = __expf(s[nt][1] - mx0);
        float e2 = __expf(s[nt][2] - mx1), e3 = __expf(s[nt][3] - mx1);
        s[nt][0] = e0; s[nt][1] = e1; s[nt][2] = e2; s[nt][3] = e3;
        sum0 += e0 + e1; sum1 += e2 + e3;
    }
    {
        float e0 = (qc == 0) ? __expf(s[36][0] - mx0) : 0.f;
        float e2 = (qc == 0) ? __expf(s[36][2] - mx1) : 0.f;
        s[36][0] = e0; s[36][1] = 0.f; s[36][2] = e2; s[36][3] = 0.f;
        sum0 += e0; sum1 += e2;
    }
    sum0 += __shfl_xor_sync(0xffffffffu, sum0, 1);
    sum0 += __shfl_xor_sync(0xffffffffu, sum0, 2);
    sum1 += __shfl_xor_sync(0xffffffffu, sum1, 1);
    sum1 += __shfl_xor_sync(0xffffffffu, sum1, 2);
    float inv0 = 1.f / sum0, inv1 = 1.f / sum1;

#pragma unroll
    for (int nt = 0; nt < 37; nt++) {
        s[nt][0] *= inv0; s[nt][1] *= inv0;
        s[nt][2] *= inv1; s[nt][3] *= inv1;
    }

    float o[8][4];
#pragma unroll
    for (int nt = 0; nt < 8; nt++)
#pragma unroll
        for (int r = 0; r < 4; r++) o[nt][r] = 0.f;

#pragma unroll
    for (int kc = 0; kc < 19; kc++) {
        const int t0 = 2 * kc, t1 = 2 * kc + 1;
        uint32_t a[4];
        a[0] = packh(s[t0][1], s[t0][0]);
        a[1] = packh(s[t0][3], s[t0][2]);
        if (t1 < 37) {
            a[2] = packh(s[t1][1], s[t1][0]);
            a[3] = packh(s[t1][3], s[t1][2]);
        } else {
            a[2] = 0u; a[3] = 0u;
        }
#pragma unroll
        for (int ntp = 0; ntp < 4; ntp++) {
            uint32_t b4[4];
            LDSM4(b4, vAddr + ntp * 9984 + kc * 32);
            mma_f16(o[2 * ntp],     a, b4);
            mma_f16(o[2 * ntp + 1], a, b4 + 2);
        }
    }

    __syncthreads();
    float* Osm = (float*)smw;   // [128][68]
#pragma unroll
    for (int nt = 0; nt < 8; nt++) {
        int col = nt * 8 + qc * 2;
        int r0 = (w * 16 + qr) * 68;
        Osm[r0 + col]              = o[nt][0];
        Osm[r0 + col + 1]          = o[nt][1];
        Osm[r0 + 8 * 68 + col]     = o[nt][2];
        Osm[r0 + 8 * 68 + col + 1] = o[nt][3];
    }
    __syncthreads();
    for (int idx = t; idx < 8192; idx += 256) {
        int tok = idx >> 6, dc = idx & 63;
        g_aoT[((long)(b * 4096 + n0 + tok)) * 512 + hh * 64 + dc] =
            __float2half_rn(Osm[tok * 68 + dc]);
    }
}

// ---------------------------------------------------------------------------
// launcher
// ---------------------------------------------------------------------------
extern "C" void kernel_launch(void* const* d_in, const int* in_sizes, int n_in,
                              void* d_out, int out_size)
{
    const float* sem  = (const float*)d_in[0];
    const float* spa  = (const float*)d_in[1];
    const float* x    = (const float*)d_in[2];
    const float* wq   = (const float*)d_in[3];
    const float* wdw  = (const float*)d_in[4];
    const float* lng  = (const float*)d_in[5];
    const float* lnb  = (const float*)d_in[6];
    const float* wpw  = (const float*)d_in[7];
    const float* wout = (const float*)d_in[8];
    float* out = (float*)d_out;

    const int GSMF = 184320;  // max over body<1> (81920) and body<2> (184320)
    const int GSM1 = 81920;
    cudaFuncSetAttribute(gemm_qkv, cudaFuncAttributeMaxDynamicSharedMemorySize, GSMF);
    cudaFuncSetAttribute(gemm_out, cudaFuncAttributeMaxDynamicSharedMemorySize, GSM1);
    cudaFuncSetAttribute(attn_kernel, cudaFuncAttributeMaxDynamicSharedMemorySize, ATTN_SMEM);

    prologue<<<NB_PRO, 256>>>(sem, spa, x, wq, wdw, wpw, wout);
    ln_kernel<<<dim3(289, 8, 2), 512>>>(lng, lnb);

    gemm_qkv<<<dim3(32, 4, 24), 256, GSMF>>>();
    attn_kernel<<<dim3(32, 64), 256, ATTN_SMEM>>>();
    gemm_out<<<dim3(32, 4, 8), 256, GSM1>>>(out);
}

// round 16
// speedup vs baseline: 1.1213x; 1.0771x over previous
#include <cuda_runtime.h>
#include <cuda_fp16.h>
#include <cstdint>
#include <math.h>

// ===========================================================================
// S2Attention on GB300 (sm_103 portable mma.sync path, fp16 numerics)
//   - fused q/k/v GEMM launch (q,k 1-pass; v 2-pass W hi/lo), ldmatrix frags
//   - attention: split-K (2 halves x 8 q-groups, 512 thr), online-softmax merge
// ===========================================================================

#define HWQ  4096
#define NKV  289

// ---------------- device scratch ----------------
__device__ __align__(256) __half g_semT [8L * 4096 * 512];  // [b][tok][512]
__device__ __align__(256) __half g_kpreT[8L * 289 * 512];
__device__ __align__(256) __half g_vpreT[8L * 289 * 512];
__device__ __align__(256) __half g_aoT  [8L * 4096 * 512];
__device__ __align__(256) __half g_qT   [8L * 4096 * 512];  // q*0.125
__device__ __align__(256) __half g_kT   [8L * 289 * 512];
__device__ __align__(256) __half g_vC   [8L * 512 * 296];   // [b][c][296] pad0
__device__ __align__(256) float  g_preK [8L * 289 * 512];   // [b][pos][c]
__device__ __align__(256) float  g_preV [8L * 289 * 512];
__device__ __align__(256) __half g_whi  [3L * 512 * 512];   // 0=wq*0.125,1=wpw,2=wout
__device__ __align__(256) __half g_wlo  [3L * 512 * 512];

// ---------------- helpers ----------------
__device__ __forceinline__ uint32_t smem_u32(const void* p) {
    uint32_t a;
    asm("{ .reg .u64 t; cvta.to.shared.u64 t, %1; cvt.u32.u64 %0, t; }"
        : "=r"(a) : "l"(p));
    return a;
}
__device__ __forceinline__ void mma_f16(float* d, const uint32_t* a, const uint32_t* b) {
    asm volatile(
        "mma.sync.aligned.m16n8k16.row.col.f32.f16.f16.f32 "
        "{%0,%1,%2,%3}, {%4,%5,%6,%7}, {%8,%9}, {%0,%1,%2,%3};"
        : "+f"(d[0]), "+f"(d[1]), "+f"(d[2]), "+f"(d[3])
        : "r"(a[0]), "r"(a[1]), "r"(a[2]), "r"(a[3]), "r"(b[0]), "r"(b[1]));
}
#define LDSM4(r, addr) \
    asm volatile("ldmatrix.sync.aligned.m8n8.x4.shared.b16 {%0,%1,%2,%3}, [%4];" \
        : "=r"((r)[0]), "=r"((r)[1]), "=r"((r)[2]), "=r"((r)[3]) : "r"(addr))
#define LDSM2(r, addr) \
    asm volatile("ldmatrix.sync.aligned.m8n8.x2.shared.b16 {%0,%1}, [%2];" \
        : "=r"((r)[0]), "=r"((r)[1]) : "r"(addr))

__device__ __forceinline__ void cpa16(uint32_t dst, const void* src, uint32_t nbytes) {
    asm volatile("cp.async.cg.shared.global [%0], [%1], 16, %2;"
                 :: "r"(dst), "l"(src), "r"(nbytes) : "memory");
}
#define CPA_COMMIT() asm volatile("cp.async.commit_group;" ::: "memory")
#define CPA_WAIT0()  asm volatile("cp.async.wait_group 0;" ::: "memory")
#define CPA_WAIT1()  asm volatile("cp.async.wait_group 1;" ::: "memory")

__device__ __forceinline__ uint32_t packh(float hi, float lo) {
    uint32_t r;
    asm("cvt.rn.f16x2.f32 %0, %1, %2;" : "=r"(r) : "f"(hi), "f"(lo));
    return r;
}

// ---------------------------------------------------------------------------
// merged prologue: [0,3072) prep_w | [3072,19456) transpose | [19456,23552) dw
// ---------------------------------------------------------------------------
#define NB_PREP 3072
#define NB_TR   16384
#define NB_DW   4096
#define NB_PRO  (NB_PREP + NB_TR + NB_DW)

__global__ __launch_bounds__(256)
void prologue(const float* __restrict__ sem, const float* __restrict__ spa,
              const float* __restrict__ x,   const float* __restrict__ wq,
              const float* __restrict__ wdw, const float* __restrict__ wpw,
              const float* __restrict__ wout)
{
    __shared__ __align__(16) char pbuf[32768];
    const int bx = blockIdx.x, t = threadIdx.x;

    if (bx < NB_PREP) {
        int i = bx * 256 + t;
        int widx = i >> 18, j = i & 262143;
        float v = (widx == 0) ? wq[j] * 0.125f : (widx == 1) ? wpw[j] : wout[j];
        __half h = __float2half_rn(v);
        g_whi[i] = h;
        g_wlo[i] = __float2half_rn(v - __half2float(h));
        return;
    }
    if (bx < NB_PREP + NB_TR) {
        float (*tile)[33] = (float(*)[33])pbuf;
        int bx2 = bx - NB_PREP;
        int b = bx2 >> 11, rem = bx2 & 2047;
        int n0 = (rem & 127) * 32, c0 = (rem >> 7) * 32;
        int tx = t & 31, ty = t >> 5;
#pragma unroll
        for (int k = 0; k < 4; k++) {
            int c = c0 + ty + 8 * k;
            tile[ty + 8 * k][tx] = sem[((long)b * 512 + c) * 4096 + n0 + tx];
        }
        __syncthreads();
#pragma unroll
        for (int k = 0; k < 4; k++) {
            int n = n0 + ty + 8 * k;
            g_semT[((long)b * 4096 + n) * 512 + c0 + tx] =
                __float2half_rn(tile[tx][ty + 8 * k]);
        }
        return;
    }
    {
        int bx3 = bx - NB_PREP - NB_TR;
        int z = bx3 >> 11, rem = bx3 & 2047;
        int b = rem >> 8, cpair = rem & 255;
        const int half = t >> 7, tl = t & 127;
        const int c = cpair * 2 + half;
        const float* in = z ? x : spa;
        float* outp = z ? g_preV : g_preK;
        float* plane = (float*)pbuf + half * 4096;
        const float4* ip = (const float4*)(in + ((long)b * 512 + c) * 4096);
#pragma unroll
        for (int i = tl; i < 1024; i += 128) ((float4*)plane)[i] = ip[i];
        float wr[16];
#pragma unroll
        for (int i = 0; i < 16; i++) wr[i] = wdw[c * 16 + i];
        __syncthreads();

        for (int pos = tl; pos < 289; pos += 128) {
            int oy = pos / 17, ox = pos - oy * 17;
            float acc = 0.f;
#pragma unroll
            for (int ky = 0; ky < 4; ky++) {
                int y = oy * 4 - 2 + ky;
                if ((unsigned)y < 64u) {
#pragma unroll
                    for (int kx = 0; kx < 4; kx++) {
                        int xx = ox * 4 - 2 + kx;
                        if ((unsigned)xx < 64u)
                            acc = fmaf(wr[ky * 4 + kx], plane[y * 64 + xx], acc);
                    }
                }
            }
            outp[((long)b * 289 + pos) * 512 + c] = acc;
        }
    }
}

// ---------------------------------------------------------------------------
// channel LayerNorm per token -> token-major fp16. grid (289,8,2), block 512
// ---------------------------------------------------------------------------
__global__ __launch_bounds__(512)
void ln_kernel(const float* __restrict__ lng, const float* __restrict__ lnb)
{
    const float* inp = blockIdx.z ? g_preV : g_preK;
    __half* oh = blockIdx.z ? g_vpreT : g_kpreT;
    const int pos = blockIdx.x, b = blockIdx.y, c = threadIdx.x;
    float acc = inp[((long)b * 289 + pos) * 512 + c];

    __shared__ float s1[16], s2[16];
    float v1 = acc, v2 = acc * acc;
#pragma unroll
    for (int o = 16; o > 0; o >>= 1) {
        v1 += __shfl_xor_sync(0xffffffffu, v1, o);
        v2 += __shfl_xor_sync(0xffffffffu, v2, o);
    }
    int w = threadIdx.x >> 5, lane = threadIdx.x & 31;
    if (lane == 0) { s1[w] = v1; s2[w] = v2; }
    __syncthreads();
    if (w == 0) {
        v1 = (lane < 16) ? s1[lane] : 0.f;
        v2 = (lane < 16) ? s2[lane] : 0.f;
#pragma unroll
        for (int o = 8; o > 0; o >>= 1) {
            v1 += __shfl_xor_sync(0xffffffffu, v1, o);
            v2 += __shfl_xor_sync(0xffffffffu, v2, o);
        }
        if (lane == 0) { s1[0] = v1; s2[0] = v2; }
    }
    __syncthreads();
    float mean = s1[0] * (1.f / 512.f);
    float var  = s2[0] * (1.f / 512.f) - mean * mean;
    float val  = (acc - mean) * rsqrtf(var + 1e-5f) * lng[c] + lnb[c];
    oh[((long)b * 289 + pos) * 512 + c] = __float2half_rn(val);
}

// ---------------------------------------------------------------------------
// GEMM body: Out[b][tok][co] = sum_ci W[co][ci] * A[b][tok][ci]
// ---------------------------------------------------------------------------
template<int PASSES>
__device__ __forceinline__
void gemm_body(char* sm, const __half* A, const __half* Whi, const __half* Wlo,
               int oselE, int b, int Ntok, float* __restrict__ extOut)
{
    constexpr int SUB    = (PASSES + 1) * 10240;
    constexpr int GSTP   = 2 * SUB;
    constexpr int STAGES = (PASSES == 1) ? 2 : 3;
    constexpr uint32_t AOFF = (PASSES == 2) ? 20480u : 10240u;
    const uint32_t smb = smem_u32(sm);
    const int t = threadIdx.x, wid = t >> 5, lane = t & 31;
    const int qr = lane >> 2, qc = lane & 3;
    const int r8 = lane & 7, g = lane >> 3, gh = g & 1, gv = g >> 1;
    const int m0 = blockIdx.y * 128, n0 = blockIdx.x * 128;
    const int wm = wid >> 2, wn = wid & 3;

    const uint32_t wRow = (uint32_t)((wm * 64 + gh * 8 + r8) * 80 + gv * 16);
    const uint32_t aRow = (uint32_t)((wn * 32 + gv * 8 + r8) * 80 + gh * 16);

    float acc[4][4][4];
#pragma unroll
    for (int i = 0; i < 4; i++)
#pragma unroll
        for (int j = 0; j < 4; j++)
#pragma unroll
            for (int k = 0; k < 4; k++) acc[i][j][k] = 0.f;

    auto load_sub = [&](int k0s, uint32_t sb) {
#pragma unroll
        for (int u = 0; u < 2; u++) {
            int q = t + 256 * u;
            int row = q >> 2, cq = q & 3;
            uint32_t soff = (uint32_t)(row * 80 + cq * 16);
            long wof = ((long)(m0 + row) << 9) + k0s + cq * 8;
            cpa16(sb + soff, Whi + wof, 16u);
            if (PASSES == 2) cpa16(sb + 10240 + soff, Wlo + wof, 16u);
            int tok = n0 + row;
            uint32_t asz = (tok < Ntok) ? 16u : 0u;
            long aof = ((long)(asz ? tok : 0) << 9) + k0s + cq * 8;
            cpa16(sb + AOFF + soff, A + aof, asz);
        }
    };
    auto load_chunk = [&](int c, int stage) {
        uint32_t sb = smb + stage * GSTP;
        load_sub(c * 64, sb);
        load_sub(c * 64 + 32, sb + SUB);
        CPA_COMMIT();
    };

    load_chunk(0, 0);
    load_chunk(1, 1);

    int stage = 0;
    for (int c = 0; c < 8; c++) {
        if (c < 7) { CPA_WAIT1(); } else { CPA_WAIT0(); }
        __syncthreads();

        if (STAGES == 3 && c + 2 < 8) {
            int ns = stage + 2; if (ns >= 3) ns -= 3;
            load_chunk(c + 2, ns);
        }

        const uint32_t stb = smb + stage * GSTP;
#pragma unroll
        for (int sub = 0; sub < 2; sub++) {
            const uint32_t subB = stb + sub * SUB;
#pragma unroll
            for (int ks = 0; ks < 2; ks++) {
                uint32_t awh[4][4], bb[4][2];
#pragma unroll
                for (int mt = 0; mt < 4; mt++)
                    LDSM4(awh[mt], subB + wRow + mt * 1280 + ks * 32);
#pragma unroll
                for (int ntp = 0; ntp < 2; ntp++) {
                    uint32_t b4[4];
                    LDSM4(b4, subB + AOFF + aRow + ntp * 1280 + ks * 32);
                    bb[2 * ntp][0]     = b4[0]; bb[2 * ntp][1]     = b4[1];
                    bb[2 * ntp + 1][0] = b4[2]; bb[2 * ntp + 1][1] = b4[3];
                }
#pragma unroll
                for (int mt = 0; mt < 4; mt++)
#pragma unroll
                    for (int nt = 0; nt < 4; nt++)
                        mma_f16(acc[mt][nt], awh[mt], bb[nt]);
                if (PASSES == 2) {
                    uint32_t awl[4][4];
#pragma unroll
                    for (int mt = 0; mt < 4; mt++)
                        LDSM4(awl[mt], subB + 10240 + wRow + mt * 1280 + ks * 32);
#pragma unroll
                    for (int mt = 0; mt < 4; mt++)
#pragma unroll
                        for (int nt = 0; nt < 4; nt++)
                            mma_f16(acc[mt][nt], awl[mt], bb[nt]);
                }
            }
        }

        if (STAGES == 2 && c + 2 < 8) {
            __syncthreads();
            load_chunk(c + 2, stage);
        }
        stage = (stage + 1 == STAGES) ? 0 : stage + 1;
    }

    __syncthreads();
    float* Osm = (float*)sm;   // [128][132]
    const bool tokmajor = (oselE < 2);
#pragma unroll
    for (int mt = 0; mt < 4; mt++) {
        int ml = wm * 64 + mt * 16 + qr;
#pragma unroll
        for (int nt = 0; nt < 4; nt++) {
            int nl = wn * 32 + nt * 8 + qc * 2;
            if (tokmajor) {
                Osm[nl * 132 + ml]           = acc[mt][nt][0];
                Osm[(nl + 1) * 132 + ml]     = acc[mt][nt][1];
                Osm[nl * 132 + ml + 8]       = acc[mt][nt][2];
                Osm[(nl + 1) * 132 + ml + 8] = acc[mt][nt][3];
            } else {
                Osm[ml * 132 + nl]           = acc[mt][nt][0];
                Osm[ml * 132 + nl + 1]       = acc[mt][nt][1];
                Osm[(ml + 8) * 132 + nl]     = acc[mt][nt][2];
                Osm[(ml + 8) * 132 + nl + 1] = acc[mt][nt][3];
            }
        }
    }
    __syncthreads();

    if (oselE <= 1) {
        __half* Oh = (oselE == 0) ? g_qT : g_kT;
#pragma unroll 4
        for (int u = 0; u < 64; u++) {
            int idx = t + 256 * u;
            int tl = idx >> 7, co = idx & 127;
            int tok = n0 + tl;
            if (tok < Ntok)
                Oh[((long)b * Ntok + tok) * 512 + m0 + co] =
                    __float2half_rn(Osm[tl * 132 + co]);
        }
    } else if (oselE == 2) {
#pragma unroll 4
        for (int u = 0; u < 64; u++) {
            int idx = t + 256 * u;
            int cl = idx >> 7, tl = idx & 127;
            int tok = n0 + tl;
            if (tok < Ntok)
                g_vC[((long)b * 512 + m0 + cl) * 296 + tok] =
                    __float2half_rn(Osm[cl * 132 + tl]);
        }
    } else {
#pragma unroll 4
        for (int u = 0; u < 64; u++) {
            int idx = t + 256 * u;
            int cl = idx >> 7, tl = idx & 127;
            extOut[((long)b * 512 + m0 + cl) * 4096 + n0 + tl] = Osm[cl * 132 + tl];
        }
    }
}

__global__ __launch_bounds__(256, 1)
void gemm_qkv()
{
    extern __shared__ char sm[];
    const int z = blockIdx.z;
    if (z < 8) {
        gemm_body<1>(sm, g_semT + (long)z * HWQ * 512, g_whi, g_wlo,
                     0, z, HWQ, nullptr);
    } else if (z < 16) {
        if (blockIdx.x >= 3) return;
        int b = z - 8;
        gemm_body<1>(sm, g_kpreT + (long)b * NKV * 512,
                     g_whi + 262144, g_wlo + 262144, 1, b, NKV, nullptr);
    } else {
        if (blockIdx.x >= 3) return;
        int b = z - 16;
        gemm_body<2>(sm, g_vpreT + (long)b * NKV * 512,
                     g_whi + 262144, g_wlo + 262144, 2, b, NKV, nullptr);
    }
}

__global__ __launch_bounds__(256, 1)
void gemm_out(float* __restrict__ out)
{
    extern __shared__ char sm[];
    const int b = blockIdx.z;
    gemm_body<1>(sm, g_aoT + (long)b * HWQ * 512,
                 g_whi + 2 * 262144, g_wlo + 2 * 262144, 3, b, HWQ, out);
}

// ---------------------------------------------------------------------------
// Split-K tensorized attention. 512 threads = 2 K-halves x 8 q-groups.
// SQ [0] 128x36w; SK [4608] 296x36w; SV [15264] 64x156w; EX [25248] 2048w.
// half0: K rows 0..143 (tiles 0..17); half1: rows 144..295 (tiles 0..18+pad).
// ---------------------------------------------------------------------------
#define SK_  4608
#define SV_  15264
#define EX_  25248
#define ATTN_SMEM ((25248 + 2048) * 4)

__global__ __launch_bounds__(512, 1)
void attn_kernel()
{
    extern __shared__ uint32_t smw[];
    uint4* s4 = (uint4*)smw;
    const int bh = blockIdx.y, b = bh >> 3, hh = bh & 7;
    const int n0 = blockIdx.x * 128;
    const int t = threadIdx.x, w = t >> 5, lane = t & 31;
    const int wq_ = w & 7, kh = w >> 3;           // q-group, K half
    const int qc = lane & 3;
    const int r8 = lane & 7, g = lane >> 3, gh = g & 1, gv = g >> 1;
    const int qr = lane >> 2;
    const uint32_t smbase = smem_u32(smw);

    {
        const uint4* q4 = (const uint4*)(g_qT + ((long)(b * 4096 + n0)) * 512 + hh * 64);
        for (int idx = t; idx < 1024; idx += 512) {
            int row = idx >> 3, j = idx & 7;
            s4[row * 9 + j] = q4[row * 64 + j];
        }
        const uint4* k4 = (const uint4*)(g_kT + ((long)b * 289) * 512 + hh * 64);
        for (int idx = t; idx < 2312; idx += 512) {
            int row = idx >> 3, j = idx & 7;
            s4[SK_ / 4 + row * 9 + j] = k4[row * 64 + j];
        }
        for (int idx = t; idx < 252; idx += 512)
            smw[SK_ + 10404 + idx] = 0;
        const uint4* v4 = (const uint4*)(g_vC + ((long)(b * 512 + hh * 64)) * 296);
        for (int idx = t; idx < 2368; idx += 512) {
            int row = idx / 37, j = idx - row * 37;
            s4[SV_ / 4 + row * 39 + j] = v4[row * 37 + j];
        }
        for (int idx = t; idx < 512; idx += 512) {
            int row = idx >> 3, ww = idx & 7;
            smw[SV_ + row * 156 + 148 + ww] = 0;
        }
    }
    __syncthreads();

    const uint32_t qAddr = smbase + (uint32_t)((wq_ * 16 + gh * 8 + r8) * 144 + gv * 16);
    const uint32_t kAddr = smbase + SK_ * 4 + (uint32_t)((gv * 8 + r8) * 144 + gh * 16);
    const uint32_t kTail = smbase + SK_ * 4 + (uint32_t)((288 + r8) * 144 + gh * 16);
    const uint32_t vAddr = smbase + SV_ * 4 + (uint32_t)((gv * 8 + r8) * 624 + gh * 16);
    const int ntp0 = kh * 9;     // K 16-row group offset for this half

    // ---- QK^T (this half) ----
    float s[20][4];
#pragma unroll
    for (int nt = 0; nt < 20; nt++)
#pragma unroll
        for (int r = 0; r < 4; r++) s[nt][r] = 0.f;

#pragma unroll
    for (int kk = 0; kk < 4; kk++) {
        uint32_t a[4];
        LDSM4(a, qAddr + kk * 32);
#pragma unroll
        for (int j = 0; j < 9; j++) {
            uint32_t b4[4];
            LDSM4(b4, kAddr + (ntp0 + j) * 2304 + kk * 32);
            mma_f16(s[2 * j],     a, b4);
            mma_f16(s[2 * j + 1], a, b4 + 2);
        }
        if (kh) {   // tail tile: K rows 288..295 (row 288 real, rest zero)
            uint32_t b2[2];
            LDSM2(b2, kTail + kk * 32);
            mma_f16(s[18], a, b2);
        }
    }

    // ---- partial softmax over this half ----
    float mx0 = -1e30f, mx1 = -1e30f;
#pragma unroll
    for (int nt = 0; nt < 18; nt++) {
        mx0 = fmaxf(mx0, fmaxf(s[nt][0], s[nt][1]));
        mx1 = fmaxf(mx1, fmaxf(s[nt][2], s[nt][3]));
    }
    if (kh && qc == 0) { mx0 = fmaxf(mx0, s[18][0]); mx1 = fmaxf(mx1, s[18][2]); }
    mx0 = fmaxf(mx0, __shfl_xor_sync(0xffffffffu, mx0, 1));
    mx0 = fmaxf(mx0, __shfl_xor_sync(0xffffffffu, mx0, 2));
    mx1 = fmaxf(mx1, __shfl_xor_sync(0xffffffffu, mx1, 1));
    mx1 = fmaxf(mx1, __shfl_xor_sync(0xffffffffu, mx1, 2));

    float sum0 = 0.f, sum1 = 0.f;
#pragma unroll
    for (int nt = 0; nt < 18; nt++) {
        float e0 = __expf(s[nt][0] - mx0), e1 = __expf(s[nt][1] - mx0);
        float e2 = __expf(s[nt][2] - mx1), e3 = __expf(s[nt][3] - mx1);
        s[nt][0] = e0; s[nt][1] = e1; s[nt][2] = e2; s[nt][3] = e3;
        sum0 += e0 + e1; sum1 += e2 + e3;
    }
    if (kh) {
        float e0 = (qc == 0) ? __expf(s[18][0] - mx0) : 0.f;
        float e2 = (qc == 0) ? __expf(s[18][2] - mx1) : 0.f;
        s[18][0] = e0; s[18][1] = 0.f; s[18][2] = e2; s[18][3] = 0.f;
        sum0 += e0; sum1 += e2;
    }
    sum0 += __shfl_xor_sync(0xffffffffu, sum0, 1);
    sum0 += __shfl_xor_sync(0xffffffffu, sum0, 2);
    sum1 += __shfl_xor_sync(0xffffffffu, sum1, 1);
    sum1 += __shfl_xor_sync(0xffffffffu, sum1, 2);

    // ---- cross-half merge via smem exchange ----
    float* exf = (float*)(smw + EX_);
    int own = ((kh * 8 + wq_) * 32 + lane) * 4;
    exf[own + 0] = mx0; exf[own + 1] = mx1;
    exf[own + 2] = sum0; exf[own + 3] = sum1;
    __syncthreads();
    int oth = (((1 - kh) * 8 + wq_) * 32 + lane) * 4;
    float omx0 = exf[oth], omx1 = exf[oth + 1];
    float os0  = exf[oth + 2], os1 = exf[oth + 3];
    float mf0 = fmaxf(mx0, omx0), mf1 = fmaxf(mx1, omx1);
    float sc0 = __expf(mx0 - mf0), sc1 = __expf(mx1 - mf1);
    float tot0 = sum0 * sc0 + os0 * __expf(omx0 - mf0);
    float tot1 = sum1 * sc1 + os1 * __expf(omx1 - mf1);
    float inv0 = sc0 / tot0, inv1 = sc1 / tot1;

#pragma unroll
    for (int nt = 0; nt < 19; nt++) {
        s[nt][0] *= inv0; s[nt][1] *= inv0;
        s[nt][2] *= inv1; s[nt][3] *= inv1;
    }

    // ---- AV over this half's V chunks ----
    float o[8][4];
#pragma unroll
    for (int nt = 0; nt < 8; nt++)
#pragma unroll
        for (int r = 0; r < 4; r++) o[nt][r] = 0.f;

#pragma unroll
    for (int j = 0; j < 9; j++) {
        uint32_t a[4];
        a[0] = packh(s[2 * j][1],     s[2 * j][0]);
        a[1] = packh(s[2 * j][3],     s[2 * j][2]);
        a[2] = packh(s[2 * j + 1][1], s[2 * j + 1][0]);
        a[3] = packh(s[2 * j + 1][3], s[2 * j + 1][2]);
#pragma unroll
        for (int ntp = 0; ntp < 4; ntp++) {
            uint32_t b4[4];
            LDSM4(b4, vAddr + ntp * 9984 + (ntp0 + j) * 32);
            mma_f16(o[2 * ntp],     a, b4);
            mma_f16(o[2 * ntp + 1], a, b4 + 2);
        }
    }
    if (kh) {   // extra chunk: kc=18 (K rows 288..303), tiles s[18], s[19]=0
        uint32_t a[4];
        a[0] = packh(s[18][1], s[18][0]);
        a[1] = packh(s[18][3], s[18][2]);
        a[2] = 0u; a[3] = 0u;
#pragma unroll
        for (int ntp = 0; ntp < 4; ntp++) {
            uint32_t b4[4];
            LDSM4(b4, vAddr + ntp * 9984 + 18 * 32);
            mma_f16(o[2 * ntp],     a, b4);
            mma_f16(o[2 * ntp + 1], a, b4 + 2);
        }
    }

    // ---- combine halves + store (token-major fp16) ----
    __syncthreads();
    float* Osm = (float*)smw;   // [128][68] = 34816 B
    if (kh == 0) {
#pragma unroll
        for (int nt = 0; nt < 8; nt++) {
            int col = nt * 8 + qc * 2;
            int r0 = (wq_ * 16 + qr) * 68;
            Osm[r0 + col]              = o[nt][0];
            Osm[r0 + col + 1]          = o[nt][1];
            Osm[r0 + 8 * 68 + col]     = o[nt][2];
            Osm[r0 + 8 * 68 + col + 1] = o[nt][3];
        }
    }
    __syncthreads();
    if (kh == 1) {
#pragma unroll
        for (int nt = 0; nt < 8; nt++) {
            int col = nt * 8 + qc * 2;
            int r0 = (wq_ * 16 + qr) * 68;
            Osm[r0 + col]              += o[nt][0];
            Osm[r0 + col + 1]          += o[nt][1];
            Osm[r0 + 8 * 68 + col]     += o[nt][2];
            Osm[r0 + 8 * 68 + col + 1] += o[nt][3];
        }
    }
    __syncthreads();
    for (int idx = t; idx < 8192; idx += 512) {
        int tok = idx >> 6, dc = idx & 63;
        g_aoT[((long)(b * 4096 + n0 + tok)) * 512 + hh * 64 + dc] =
            __float2half_rn(Osm[tok * 68 + dc]);
    }
}

// ---------------------------------------------------------------------------
// launcher
// ---------------------------------------------------------------------------
extern "C" void kernel_launch(void* const* d_in, const int* in_sizes, int n_in,
                              void* d_out, int out_size)
{
    const float* sem  = (const float*)d_in[0];
    const float* spa  = (const float*)d_in[1];
    const float* x    = (const float*)d_in[2];
    const float* wq   = (const float*)d_in[3];
    const float* wdw  = (const float*)d_in[4];
    const float* lng  = (const float*)d_in[5];
    const float* lnb  = (const float*)d_in[6];
    const float* wpw  = (const float*)d_in[7];
    const float* wout = (const float*)d_in[8];
    float* out = (float*)d_out;

    const int GSMF = 184320;
    const int GSM1 = 81920;
    cudaFuncSetAttribute(gemm_qkv, cudaFuncAttributeMaxDynamicSharedMemorySize, GSMF);
    cudaFuncSetAttribute(gemm_out, cudaFuncAttributeMaxDynamicSharedMemorySize, GSM1);
    cudaFuncSetAttribute(attn_kernel, cudaFuncAttributeMaxDynamicSharedMemorySize, ATTN_SMEM);

    prologue<<<NB_PRO, 256>>>(sem, spa, x, wq, wdw, wpw, wout);
    ln_kernel<<<dim3(289, 8, 2), 512>>>(lng, lnb);

    gemm_qkv<<<dim3(32, 4, 24), 256, GSMF>>>();
    attn_kernel<<<dim3(32, 64), 512, ATTN_SMEM>>>();
    gemm_out<<<dim3(32, 4, 8), 256, GSM1>>>(out);
}

// round 17
// speedup vs baseline: 1.1969x; 1.0674x over previous
#include <cuda_runtime.h>
#include <cuda_fp16.h>
#include <cstdint>
#include <math.h>

// ===========================================================================
// S2Attention on GB300 (sm_103 portable mma.sync path, fp16 numerics)
//   - fused q/k/v GEMM launch @ 2 blocks/SM (launch_bounds cap 128 regs)
//   - attention: split-K (2 halves x 8 q-groups, 512 thr), online-softmax merge
// ===========================================================================

#define HWQ  4096
#define NKV  289

// ---------------- device scratch ----------------
__device__ __align__(256) __half g_semT [8L * 4096 * 512];  // [b][tok][512]
__device__ __align__(256) __half g_kpreT[8L * 289 * 512];
__device__ __align__(256) __half g_vpreT[8L * 289 * 512];
__device__ __align__(256) __half g_aoT  [8L * 4096 * 512];
__device__ __align__(256) __half g_qT   [8L * 4096 * 512];  // q*0.125
__device__ __align__(256) __half g_kT   [8L * 289 * 512];
__device__ __align__(256) __half g_vC   [8L * 512 * 296];   // [b][c][296] pad0
__device__ __align__(256) float  g_preK [8L * 289 * 512];   // [b][pos][c]
__device__ __align__(256) float  g_preV [8L * 289 * 512];
__device__ __align__(256) __half g_whi  [3L * 512 * 512];   // 0=wq*0.125,1=wpw,2=wout
__device__ __align__(256) __half g_wlo  [3L * 512 * 512];

// ---------------- helpers ----------------
__device__ __forceinline__ uint32_t smem_u32(const void* p) {
    uint32_t a;
    asm("{ .reg .u64 t; cvta.to.shared.u64 t, %1; cvt.u32.u64 %0, t; }"
        : "=r"(a) : "l"(p));
    return a;
}
__device__ __forceinline__ void mma_f16(float* d, const uint32_t* a, const uint32_t* b) {
    asm volatile(
        "mma.sync.aligned.m16n8k16.row.col.f32.f16.f16.f32 "
        "{%0,%1,%2,%3}, {%4,%5,%6,%7}, {%8,%9}, {%0,%1,%2,%3};"
        : "+f"(d[0]), "+f"(d[1]), "+f"(d[2]), "+f"(d[3])
        : "r"(a[0]), "r"(a[1]), "r"(a[2]), "r"(a[3]), "r"(b[0]), "r"(b[1]));
}
#define LDSM4(r, addr) \
    asm volatile("ldmatrix.sync.aligned.m8n8.x4.shared.b16 {%0,%1,%2,%3}, [%4];" \
        : "=r"((r)[0]), "=r"((r)[1]), "=r"((r)[2]), "=r"((r)[3]) : "r"(addr))
#define LDSM2(r, addr) \
    asm volatile("ldmatrix.sync.aligned.m8n8.x2.shared.b16 {%0,%1}, [%2];" \
        : "=r"((r)[0]), "=r"((r)[1]) : "r"(addr))

__device__ __forceinline__ void cpa16(uint32_t dst, const void* src, uint32_t nbytes) {
    asm volatile("cp.async.cg.shared.global [%0], [%1], 16, %2;"
                 :: "r"(dst), "l"(src), "r"(nbytes) : "memory");
}
#define CPA_COMMIT() asm volatile("cp.async.commit_group;" ::: "memory")
#define CPA_WAIT0()  asm volatile("cp.async.wait_group 0;" ::: "memory")
#define CPA_WAIT1()  asm volatile("cp.async.wait_group 1;" ::: "memory")

__device__ __forceinline__ uint32_t packh(float hi, float lo) {
    uint32_t r;
    asm("cvt.rn.f16x2.f32 %0, %1, %2;" : "=r"(r) : "f"(hi), "f"(lo));
    return r;
}

// ---------------------------------------------------------------------------
// merged prologue: [0,3072) prep_w | [3072,19456) transpose | [19456,23552) dw
// ---------------------------------------------------------------------------
#define NB_PREP 3072
#define NB_TR   16384
#define NB_DW   4096
#define NB_PRO  (NB_PREP + NB_TR + NB_DW)

__global__ __launch_bounds__(256)
void prologue(const float* __restrict__ sem, const float* __restrict__ spa,
              const float* __restrict__ x,   const float* __restrict__ wq,
              const float* __restrict__ wdw, const float* __restrict__ wpw,
              const float* __restrict__ wout)
{
    __shared__ __align__(16) char pbuf[32768];
    const int bx = blockIdx.x, t = threadIdx.x;

    if (bx < NB_PREP) {
        int i = bx * 256 + t;
        int widx = i >> 18, j = i & 262143;
        float v = (widx == 0) ? wq[j] * 0.125f : (widx == 1) ? wpw[j] : wout[j];
        __half h = __float2half_rn(v);
        g_whi[i] = h;
        g_wlo[i] = __float2half_rn(v - __half2float(h));
        return;
    }
    if (bx < NB_PREP + NB_TR) {
        float (*tile)[33] = (float(*)[33])pbuf;
        int bx2 = bx - NB_PREP;
        int b = bx2 >> 11, rem = bx2 & 2047;
        int n0 = (rem & 127) * 32, c0 = (rem >> 7) * 32;
        int tx = t & 31, ty = t >> 5;
#pragma unroll
        for (int k = 0; k < 4; k++) {
            int c = c0 + ty + 8 * k;
            tile[ty + 8 * k][tx] = sem[((long)b * 512 + c) * 4096 + n0 + tx];
        }
        __syncthreads();
#pragma unroll
        for (int k = 0; k < 4; k++) {
            int n = n0 + ty + 8 * k;
            g_semT[((long)b * 4096 + n) * 512 + c0 + tx] =
                __float2half_rn(tile[tx][ty + 8 * k]);
        }
        return;
    }
    {
        int bx3 = bx - NB_PREP - NB_TR;
        int z = bx3 >> 11, rem = bx3 & 2047;
        int b = rem >> 8, cpair = rem & 255;
        const int half = t >> 7, tl = t & 127;
        const int c = cpair * 2 + half;
        const float* in = z ? x : spa;
        float* outp = z ? g_preV : g_preK;
        float* plane = (float*)pbuf + half * 4096;
        const float4* ip = (const float4*)(in + ((long)b * 512 + c) * 4096);
#pragma unroll
        for (int i = tl; i < 1024; i += 128) ((float4*)plane)[i] = ip[i];
        float wr[16];
#pragma unroll
        for (int i = 0; i < 16; i++) wr[i] = wdw[c * 16 + i];
        __syncthreads();

        for (int pos = tl; pos < 289; pos += 128) {
            int oy = pos / 17, ox = pos - oy * 17;
            float acc = 0.f;
#pragma unroll
            for (int ky = 0; ky < 4; ky++) {
                int y = oy * 4 - 2 + ky;
                if ((unsigned)y < 64u) {
#pragma unroll
                    for (int kx = 0; kx < 4; kx++) {
                        int xx = ox * 4 - 2 + kx;
                        if ((unsigned)xx < 64u)
                            acc = fmaf(wr[ky * 4 + kx], plane[y * 64 + xx], acc);
                    }
                }
            }
            outp[((long)b * 289 + pos) * 512 + c] = acc;
        }
    }
}

// ---------------------------------------------------------------------------
// channel LayerNorm per token -> token-major fp16. grid (289,8,2), block 512
// ---------------------------------------------------------------------------
__global__ __launch_bounds__(512)
void ln_kernel(const float* __restrict__ lng, const float* __restrict__ lnb)
{
    const float* inp = blockIdx.z ? g_preV : g_preK;
    __half* oh = blockIdx.z ? g_vpreT : g_kpreT;
    const int pos = blockIdx.x, b = blockIdx.y, c = threadIdx.x;
    float acc = inp[((long)b * 289 + pos) * 512 + c];

    __shared__ float s1[16], s2[16];
    float v1 = acc, v2 = acc * acc;
#pragma unroll
    for (int o = 16; o > 0; o >>= 1) {
        v1 += __shfl_xor_sync(0xffffffffu, v1, o);
        v2 += __shfl_xor_sync(0xffffffffu, v2, o);
    }
    int w = threadIdx.x >> 5, lane = threadIdx.x & 31;
    if (lane == 0) { s1[w] = v1; s2[w] = v2; }
    __syncthreads();
    if (w == 0) {
        v1 = (lane < 16) ? s1[lane] : 0.f;
        v2 = (lane < 16) ? s2[lane] : 0.f;
#pragma unroll
        for (int o = 8; o > 0; o >>= 1) {
            v1 += __shfl_xor_sync(0xffffffffu, v1, o);
            v2 += __shfl_xor_sync(0xffffffffu, v2, o);
        }
        if (lane == 0) { s1[0] = v1; s2[0] = v2; }
    }
    __syncthreads();
    float mean = s1[0] * (1.f / 512.f);
    float var  = s2[0] * (1.f / 512.f) - mean * mean;
    float val  = (acc - mean) * rsqrtf(var + 1e-5f) * lng[c] + lnb[c];
    oh[((long)b * 289 + pos) * 512 + c] = __float2half_rn(val);
}

// ---------------------------------------------------------------------------
// shared GEMM epilogue
// ---------------------------------------------------------------------------
__device__ __forceinline__
void gemm_epilogue(char* sm, float acc[4][4][4], int oselE, int b, int Ntok,
                   float* __restrict__ extOut)
{
    const int t = threadIdx.x, wid = t >> 5, lane = t & 31;
    const int qr = lane >> 2, qc = lane & 3;
    const int m0 = blockIdx.y * 128, n0 = blockIdx.x * 128;
    const int wm = wid >> 2, wn = wid & 3;

    __syncthreads();
    float* Osm = (float*)sm;   // [128][132] = 67584 B
    const bool tokmajor = (oselE < 2);
#pragma unroll
    for (int mt = 0; mt < 4; mt++) {
        int ml = wm * 64 + mt * 16 + qr;
#pragma unroll
        for (int nt = 0; nt < 4; nt++) {
            int nl = wn * 32 + nt * 8 + qc * 2;
            if (tokmajor) {
                Osm[nl * 132 + ml]           = acc[mt][nt][0];
                Osm[(nl + 1) * 132 + ml]     = acc[mt][nt][1];
                Osm[nl * 132 + ml + 8]       = acc[mt][nt][2];
                Osm[(nl + 1) * 132 + ml + 8] = acc[mt][nt][3];
            } else {
                Osm[ml * 132 + nl]           = acc[mt][nt][0];
                Osm[ml * 132 + nl + 1]       = acc[mt][nt][1];
                Osm[(ml + 8) * 132 + nl]     = acc[mt][nt][2];
                Osm[(ml + 8) * 132 + nl + 1] = acc[mt][nt][3];
            }
        }
    }
    __syncthreads();

    if (oselE <= 1) {
        __half* Oh = (oselE == 0) ? g_qT : g_kT;
#pragma unroll 4
        for (int u = 0; u < 64; u++) {
            int idx = t + 256 * u;
            int tl = idx >> 7, co = idx & 127;
            int tok = n0 + tl;
            if (tok < Ntok)
                Oh[((long)b * Ntok + tok) * 512 + m0 + co] =
                    __float2half_rn(Osm[tl * 132 + co]);
        }
    } else if (oselE == 2) {
#pragma unroll 4
        for (int u = 0; u < 64; u++) {
            int idx = t + 256 * u;
            int cl = idx >> 7, tl = idx & 127;
            int tok = n0 + tl;
            if (tok < Ntok)
                g_vC[((long)b * 512 + m0 + cl) * 296 + tok] =
                    __float2half_rn(Osm[cl * 132 + tl]);
        }
    } else {
#pragma unroll 4
        for (int u = 0; u < 64; u++) {
            int idx = t + 256 * u;
            int cl = idx >> 7, tl = idx & 127;
            extOut[((long)b * 512 + m0 + cl) * 4096 + n0 + tl] = Osm[cl * 132 + tl];
        }
    }
}

// ---------------------------------------------------------------------------
// GEMM body (1-pass W): K-chunk 64 = 2x 32-k subtiles, 2 stages (81920 B)
// ---------------------------------------------------------------------------
__device__ __forceinline__
void gemm_body1(char* sm, const __half* A, const __half* Whi,
                int oselE, int b, int Ntok, float* __restrict__ extOut)
{
    constexpr int SUB  = 20480;
    constexpr int GSTP = 40960;
    const uint32_t smb = smem_u32(sm);
    const int t = threadIdx.x, wid = t >> 5, lane = t & 31;
    const int r8 = lane & 7, g = lane >> 3, gh = g & 1, gv = g >> 1;
    const int m0 = blockIdx.y * 128, n0 = blockIdx.x * 128;
    const int wm = wid >> 2, wn = wid & 3;

    const uint32_t wRow = (uint32_t)((wm * 64 + gh * 8 + r8) * 80 + gv * 16);
    const uint32_t aRow = (uint32_t)((wn * 32 + gv * 8 + r8) * 80 + gh * 16);

    float acc[4][4][4];
#pragma unroll
    for (int i = 0; i < 4; i++)
#pragma unroll
        for (int j = 0; j < 4; j++)
#pragma unroll
            for (int k = 0; k < 4; k++) acc[i][j][k] = 0.f;

    auto load_sub = [&](int k0s, uint32_t sb) {
#pragma unroll
        for (int u = 0; u < 2; u++) {
            int q = t + 256 * u;
            int row = q >> 2, cq = q & 3;
            uint32_t soff = (uint32_t)(row * 80 + cq * 16);
            long wof = ((long)(m0 + row) << 9) + k0s + cq * 8;
            cpa16(sb + soff, Whi + wof, 16u);
            int tok = n0 + row;
            uint32_t asz = (tok < Ntok) ? 16u : 0u;
            long aof = ((long)(asz ? tok : 0) << 9) + k0s + cq * 8;
            cpa16(sb + 10240 + soff, A + aof, asz);
        }
    };
    auto load_chunk = [&](int c, int stage) {
        uint32_t sb = smb + stage * GSTP;
        load_sub(c * 64, sb);
        load_sub(c * 64 + 32, sb + SUB);
        CPA_COMMIT();
    };

    load_chunk(0, 0);
    load_chunk(1, 1);

    int stage = 0;
    for (int c = 0; c < 8; c++) {
        if (c < 7) { CPA_WAIT1(); } else { CPA_WAIT0(); }
        __syncthreads();

        const uint32_t stb = smb + stage * GSTP;
#pragma unroll
        for (int sub = 0; sub < 2; sub++) {
            const uint32_t subB = stb + sub * SUB;
#pragma unroll
            for (int ks = 0; ks < 2; ks++) {
                uint32_t awh[4][4], bb[4][2];
#pragma unroll
                for (int mt = 0; mt < 4; mt++)
                    LDSM4(awh[mt], subB + wRow + mt * 1280 + ks * 32);
#pragma unroll
                for (int ntp = 0; ntp < 2; ntp++) {
                    uint32_t b4[4];
                    LDSM4(b4, subB + 10240 + aRow + ntp * 1280 + ks * 32);
                    bb[2 * ntp][0]     = b4[0]; bb[2 * ntp][1]     = b4[1];
                    bb[2 * ntp + 1][0] = b4[2]; bb[2 * ntp + 1][1] = b4[3];
                }
#pragma unroll
                for (int mt = 0; mt < 4; mt++)
#pragma unroll
                    for (int nt = 0; nt < 4; nt++)
                        mma_f16(acc[mt][nt], awh[mt], bb[nt]);
            }
        }
        if (c + 2 < 8) {
            __syncthreads();
            load_chunk(c + 2, stage);
        }
        stage ^= 1;
    }
    gemm_epilogue(sm, acc, oselE, b, Ntok, extOut);
}

// ---------------------------------------------------------------------------
// GEMM body v (2-pass W hi/lo): K-chunk 32, 2 stages (61440 B <= 81920)
// ---------------------------------------------------------------------------
__device__ __forceinline__
void gemm_body_v(char* sm, const __half* A, const __half* Whi, const __half* Wlo,
                 int b, int Ntok)
{
    constexpr int GSTP = 30720;    // [Whi 10240][Wlo 10240][A 10240]
    const uint32_t smb = smem_u32(sm);
    const int t = threadIdx.x, wid = t >> 5, lane = t & 31;
    const int r8 = lane & 7, g = lane >> 3, gh = g & 1, gv = g >> 1;
    const int m0 = blockIdx.y * 128, n0 = blockIdx.x * 128;
    const int wm = wid >> 2, wn = wid & 3;

    const uint32_t wRow = (uint32_t)((wm * 64 + gh * 8 + r8) * 80 + gv * 16);
    const uint32_t aRow = (uint32_t)((wn * 32 + gv * 8 + r8) * 80 + gh * 16);

    float acc[4][4][4];
#pragma unroll
    for (int i = 0; i < 4; i++)
#pragma unroll
        for (int j = 0; j < 4; j++)
#pragma unroll
            for (int k = 0; k < 4; k++) acc[i][j][k] = 0.f;

    auto load_chunk = [&](int c, int stage) {
        const int k0s = c * 32;
        const uint32_t sb = smb + stage * GSTP;
#pragma unroll
        for (int u = 0; u < 2; u++) {
            int q = t + 256 * u;
            int row = q >> 2, cq = q & 3;
            uint32_t soff = (uint32_t)(row * 80 + cq * 16);
            long wof = ((long)(m0 + row) << 9) + k0s + cq * 8;
            cpa16(sb + soff, Whi + wof, 16u);
            cpa16(sb + 10240 + soff, Wlo + wof, 16u);
            int tok = n0 + row;
            uint32_t asz = (tok < Ntok) ? 16u : 0u;
            long aof = ((long)(asz ? tok : 0) << 9) + k0s + cq * 8;
            cpa16(sb + 20480 + soff, A + aof, asz);
        }
        CPA_COMMIT();
    };

    load_chunk(0, 0);
    load_chunk(1, 1);

    int stage = 0;
    for (int c = 0; c < 16; c++) {
        if (c < 15) { CPA_WAIT1(); } else { CPA_WAIT0(); }
        __syncthreads();

        const uint32_t subB = smb + stage * GSTP;
#pragma unroll
        for (int ks = 0; ks < 2; ks++) {
            uint32_t awh[4][4], awl[4][4], bb[4][2];
#pragma unroll
            for (int mt = 0; mt < 4; mt++) {
                LDSM4(awh[mt], subB + wRow + mt * 1280 + ks * 32);
                LDSM4(awl[mt], subB + 10240 + wRow + mt * 1280 + ks * 32);
            }
#pragma unroll
            for (int ntp = 0; ntp < 2; ntp++) {
                uint32_t b4[4];
                LDSM4(b4, subB + 20480 + aRow + ntp * 1280 + ks * 32);
                bb[2 * ntp][0]     = b4[0]; bb[2 * ntp][1]     = b4[1];
                bb[2 * ntp + 1][0] = b4[2]; bb[2 * ntp + 1][1] = b4[3];
            }
#pragma unroll
            for (int mt = 0; mt < 4; mt++)
#pragma unroll
                for (int nt = 0; nt < 4; nt++) {
                    mma_f16(acc[mt][nt], awh[mt], bb[nt]);
                    mma_f16(acc[mt][nt], awl[mt], bb[nt]);
                }
        }
        if (c + 2 < 16) {
            __syncthreads();
            load_chunk(c + 2, stage);
        }
        stage ^= 1;
    }
    gemm_epilogue(sm, acc, 2, b, Ntok, nullptr);
}

// fused q + k + v GEMM launch. grid (32, 4, 24), 2 blocks/SM.
__global__ __launch_bounds__(256, 2)
void gemm_qkv()
{
    extern __shared__ char sm[];
    const int z = blockIdx.z;
    if (z < 8) {
        gemm_body1(sm, g_semT + (long)z * HWQ * 512, g_whi, 0, z, HWQ, nullptr);
    } else if (z < 16) {
        if (blockIdx.x >= 3) return;
        int b = z - 8;
        gemm_body1(sm, g_kpreT + (long)b * NKV * 512, g_whi + 262144,
                   1, b, NKV, nullptr);
    } else {
        if (blockIdx.x >= 3) return;
        int b = z - 16;
        gemm_body_v(sm, g_vpreT + (long)b * NKV * 512,
                    g_whi + 262144, g_wlo + 262144, b, NKV);
    }
}

__global__ __launch_bounds__(256, 2)
void gemm_out(float* __restrict__ out)
{
    extern __shared__ char sm[];
    const int b = blockIdx.z;
    gemm_body1(sm, g_aoT + (long)b * HWQ * 512, g_whi + 2 * 262144,
               3, b, HWQ, out);
}

// ---------------------------------------------------------------------------
// Split-K tensorized attention. 512 threads = 2 K-halves x 8 q-groups.
// ---------------------------------------------------------------------------
#define SK_  4608
#define SV_  15264
#define EX_  25248
#define ATTN_SMEM ((25248 + 2048) * 4)

__global__ __launch_bounds__(512, 1)
void attn_kernel()
{
    extern __shared__ uint32_t smw[];
    uint4* s4 = (uint4*)smw;
    const int bh = blockIdx.y, b = bh >> 3, hh = bh & 7;
    const int n0 = blockIdx.x * 128;
    const int t = threadIdx.x, w = t >> 5, lane = t & 31;
    const int wq_ = w & 7, kh = w >> 3;
    const int qc = lane & 3;
    const int r8 = lane & 7, g = lane >> 3, gh = g & 1, gv = g >> 1;
    const int qr = lane >> 2;
    const uint32_t smbase = smem_u32(smw);

    {
        const uint4* q4 = (const uint4*)(g_qT + ((long)(b * 4096 + n0)) * 512 + hh * 64);
        for (int idx = t; idx < 1024; idx += 512) {
            int row = idx >> 3, j = idx & 7;
            s4[row * 9 + j] = q4[row * 64 + j];
        }
        const uint4* k4 = (const uint4*)(g_kT + ((long)b * 289) * 512 + hh * 64);
        for (int idx = t; idx < 2312; idx += 512) {
            int row = idx >> 3, j = idx & 7;
            s4[SK_ / 4 + row * 9 + j] = k4[row * 64 + j];
        }
        for (int idx = t; idx < 252; idx += 512)
            smw[SK_ + 10404 + idx] = 0;
        const uint4* v4 = (const uint4*)(g_vC + ((long)(b * 512 + hh * 64)) * 296);
        for (int idx = t; idx < 2368; idx += 512) {
            int row = idx / 37, j = idx - row * 37;
            s4[SV_ / 4 + row * 39 + j] = v4[row * 37 + j];
        }
        for (int idx = t; idx < 512; idx += 512) {
            int row = idx >> 3, ww = idx & 7;
            smw[SV_ + row * 156 + 148 + ww] = 0;
        }
    }
    __syncthreads();

    const uint32_t qAddr = smbase + (uint32_t)((wq_ * 16 + gh * 8 + r8) * 144 + gv * 16);
    const uint32_t kAddr = smbase + SK_ * 4 + (uint32_t)((gv * 8 + r8) * 144 + gh * 16);
    const uint32_t kTail = smbase + SK_ * 4 + (uint32_t)((288 + r8) * 144 + gh * 16);
    const uint32_t vAddr = smbase + SV_ * 4 + (uint32_t)((gv * 8 + r8) * 624 + gh * 16);
    const int ntp0 = kh * 9;

    float s[20][4];
#pragma unroll
    for (int nt = 0; nt < 20; nt++)
#pragma unroll
        for (int r = 0; r < 4; r++) s[nt][r] = 0.f;

#pragma unroll
    for (int kk = 0; kk < 4; kk++) {
        uint32_t a[4];
        LDSM4(a, qAddr + kk * 32);
#pragma unroll
        for (int j = 0; j < 9; j++) {
            uint32_t b4[4];
            LDSM4(b4, kAddr + (ntp0 + j) * 2304 + kk * 32);
            mma_f16(s[2 * j],     a, b4);
            mma_f16(s[2 * j + 1], a, b4 + 2);
        }
        if (kh) {
            uint32_t b2[2];
            LDSM2(b2, kTail + kk * 32);
            mma_f16(s[18], a, b2);
        }
    }

    float mx0 = -1e30f, mx1 = -1e30f;
#pragma unroll
    for (int nt = 0; nt < 18; nt++) {
        mx0 = fmaxf(mx0, fmaxf(s[nt][0], s[nt][1]));
        mx1 = fmaxf(mx1, fmaxf(s[nt][2], s[nt][3]));
    }
    if (kh && qc == 0) { mx0 = fmaxf(mx0, s[18][0]); mx1 = fmaxf(mx1, s[18][2]); }
    mx0 = fmaxf(mx0, __shfl_xor_sync(0xffffffffu, mx0, 1));
    mx0 = fmaxf(mx0, __shfl_xor_sync(0xffffffffu, mx0, 2));
    mx1 = fmaxf(mx1, __shfl_xor_sync(0xffffffffu, mx1, 1));
    mx1 = fmaxf(mx1, __shfl_xor_sync(0xffffffffu, mx1, 2));

    float sum0 = 0.f, sum1 = 0.f;
#pragma unroll
    for (int nt = 0; nt < 18; nt++) {
        float e0 = __expf(s[nt][0] - mx0), e1 = __expf(s[nt][1] - mx0);
        float e2 = __expf(s[nt][2] - mx1), e3 = __expf(s[nt][3] - mx1);
        s[nt][0] = e0; s[nt][1] = e1; s[nt][2] = e2; s[nt][3] = e3;
        sum0 += e0 + e1; sum1 += e2 + e3;
    }
    if (kh) {
        float e0 = (qc == 0) ? __expf(s[18][0] - mx0) : 0.f;
        float e2 = (qc == 0) ? __expf(s[18][2] - mx1) : 0.f;
        s[18][0] = e0; s[18][1] = 0.f; s[18][2] = e2; s[18][3] = 0.f;
        sum0 += e0; sum1 += e2;
    }
    sum0 += __shfl_xor_sync(0xffffffffu, sum0, 1);
    sum0 += __shfl_xor_sync(0xffffffffu, sum0, 2);
    sum1 += __shfl_xor_sync(0xffffffffu, sum1, 1);
    sum1 += __shfl_xor_sync(0xffffffffu, sum1, 2);

    float* exf = (float*)(smw + EX_);
    int own = ((kh * 8 + wq_) * 32 + lane) * 4;
    exf[own + 0] = mx0; exf[own + 1] = mx1;
    exf[own + 2] = sum0; exf[own + 3] = sum1;
    __syncthreads();
    int oth = (((1 - kh) * 8 + wq_) * 32 + lane) * 4;
    float omx0 = exf[oth], omx1 = exf[oth + 1];
    float os0  = exf[oth + 2], os1 = exf[oth + 3];
    float mf0 = fmaxf(mx0, omx0), mf1 = fmaxf(mx1, omx1);
    float sc0 = __expf(mx0 - mf0), sc1 = __expf(mx1 - mf1);
    float tot0 = sum0 * sc0 + os0 * __expf(omx0 - mf0);
    float tot1 = sum1 * sc1 + os1 * __expf(omx1 - mf1);
    float inv0 = sc0 / tot0, inv1 = sc1 / tot1;

#pragma unroll
    for (int nt = 0; nt < 19; nt++) {
        s[nt][0] *= inv0; s[nt][1] *= inv0;
        s[nt][2] *= inv1; s[nt][3] *= inv1;
    }

    float o[8][4];
#pragma unroll
    for (int nt = 0; nt < 8; nt++)
#pragma unroll
        for (int r = 0; r < 4; r++) o[nt][r] = 0.f;

#pragma unroll
    for (int j = 0; j < 9; j++) {
        uint32_t a[4];
        a[0] = packh(s[2 * j][1],     s[2 * j][0]);
        a[1] = packh(s[2 * j][3],     s[2 * j][2]);
        a[2] = packh(s[2 * j + 1][1], s[2 * j + 1][0]);
        a[3] = packh(s[2 * j + 1][3], s[2 * j + 1][2]);
#pragma unroll
        for (int ntp = 0; ntp < 4; ntp++) {
            uint32_t b4[4];
            LDSM4(b4, vAddr + ntp * 9984 + (ntp0 + j) * 32);
            mma_f16(o[2 * ntp],     a, b4);
            mma_f16(o[2 * ntp + 1], a, b4 + 2);
        }
    }
    if (kh) {
        uint32_t a[4];
        a[0] = packh(s[18][1], s[18][0]);
        a[1] = packh(s[18][3], s[18][2]);
        a[2] = 0u; a[3] = 0u;
#pragma unroll
        for (int ntp = 0; ntp < 4; ntp++) {
            uint32_t b4[4];
            LDSM4(b4, vAddr + ntp * 9984 + 18 * 32);
            mma_f16(o[2 * ntp],     a, b4);
            mma_f16(o[2 * ntp + 1], a, b4 + 2);
        }
    }

    __syncthreads();
    float* Osm = (float*)smw;   // [128][68]
    if (kh == 0) {
#pragma unroll
        for (int nt = 0; nt < 8; nt++) {
            int col = nt * 8 + qc * 2;
            int r0 = (wq_ * 16 + qr) * 68;
            Osm[r0 + col]              = o[nt][0];
            Osm[r0 + col + 1]          = o[nt][1];
            Osm[r0 + 8 * 68 + col]     = o[nt][2];
            Osm[r0 + 8 * 68 + col + 1] = o[nt][3];
        }
    }
    __syncthreads();
    if (kh == 1) {
#pragma unroll
        for (int nt = 0; nt < 8; nt++) {
            int col = nt * 8 + qc * 2;
            int r0 = (wq_ * 16 + qr) * 68;
            Osm[r0 + col]              += o[nt][0];
            Osm[r0 + col + 1]          += o[nt][1];
            Osm[r0 + 8 * 68 + col]     += o[nt][2];
            Osm[r0 + 8 * 68 + col + 1] += o[nt][3];
        }
    }
    __syncthreads();
    for (int idx = t; idx < 8192; idx += 512) {
        int tok = idx >> 6, dc = idx & 63;
        g_aoT[((long)(b * 4096 + n0 + tok)) * 512 + hh * 64 + dc] =
            __float2half_rn(Osm[tok * 68 + dc]);
    }
}

// ---------------------------------------------------------------------------
// launcher
// ---------------------------------------------------------------------------
extern "C" void kernel_launch(void* const* d_in, const int* in_sizes, int n_in,
                              void* d_out, int out_size)
{
    const float* sem  = (const float*)d_in[0];
    const float* spa  = (const float*)d_in[1];
    const float* x    = (const float*)d_in[2];
    const float* wq   = (const float*)d_in[3];
    const float* wdw  = (const float*)d_in[4];
    const float* lng  = (const float*)d_in[5];
    const float* lnb  = (const float*)d_in[6];
    const float* wpw  = (const float*)d_in[7];
    const float* wout = (const float*)d_in[8];
    float* out = (float*)d_out;

    const int GSM = 81920;   // both bodies fit; 2 blocks/SM
    cudaFuncSetAttribute(gemm_qkv, cudaFuncAttributeMaxDynamicSharedMemorySize, GSM);
    cudaFuncSetAttribute(gemm_out, cudaFuncAttributeMaxDynamicSharedMemorySize, GSM);
    cudaFuncSetAttribute(attn_kernel, cudaFuncAttributeMaxDynamicSharedMemorySize, ATTN_SMEM);

    prologue<<<NB_PRO, 256>>>(sem, spa, x, wq, wdw, wpw, wout);
    ln_kernel<<<dim3(289, 8, 2), 512>>>(lng, lnb);

    gemm_qkv<<<dim3(32, 4, 24), 256, GSM>>>();
    attn_kernel<<<dim3(32, 64), 512, ATTN_SMEM>>>();
    gemm_out<<<dim3(32, 4, 8), 256, GSM>>>(out);
}